// round 11
// baseline (speedup 1.0000x reference)
#include <cuda_runtime.h>
#include <cuda_bf16.h>
#include <cstdint>

// CameraSpline pose evaluation.
// Inputs (metadata order): t [M] f32, ctrl_trans [K,3] f32, ctrl_quats [K,4] f32, N [1] i32.
// Output: R [M,3,3] flattened (9*M floats) followed by T [M,3] (3*M floats).
//
// R10 -> R11: persistent warps + cp.async double-buffered record staging.
// R10 held 16 float4 of prefetched records in registers -> 96 regs, occ 27.8%.
// Now records stream global->smem via cp.async.cg (LDGSTS: no register
// roundtrip, L1 bypass) with a 2-chunk pipeline per warp; regs return to ~45.
// Outputs stage into the just-consumed buffer; per-chunk coalesced writeback.

#define TPB 128
#define WARPS (TPB / 32)
#define CAPI 524288                // max intervals in the record table

#define CP_ASYNC16(dst32, src)                                              \
    asm volatile("cp.async.cg.shared.global [%0], [%1], 16;"                \
                 :: "r"(dst32), "l"(src) : "memory")
#define CP_ASYNC_COMMIT() asm volatile("cp.async.commit_group;" ::: "memory")
#define CP_ASYNC_WAIT(n)  asm volatile("cp.async.wait_group %0;" :: "n"(n) : "memory")

// One 128B record (8 float4 parts) per interval i:
//  p0: p0x p0y p0z m0x | p1: m0y m0z p1x p1y | p2: p1z m1x m1y m1z
//  p3: q_i | p4: q_i1_adj (sign folded) | p5: thm ism tha isa
//  p6: q_im1 | p7: q_ip2_adj (sign folded)
__device__ __align__(128) float4 g_rec[(size_t)CAPI * 8];

__device__ __forceinline__ float4 qnormalize(float4 q) {
    float inv = rsqrtf(q.x * q.x + q.y * q.y + q.z * q.z + q.w * q.w);
    return make_float4(q.x * inv, q.y * inv, q.z * inv, q.w * inv);
}

// acos(x) for x in [0,1]: sqrt(1-x) * poly7 (Hastings; |err| ~ 2e-8).
__device__ __forceinline__ float facos01(float x) {
    float p = fmaf(x, -0.0012624911f, 0.0066700901f);
    p = fmaf(x, p, -0.0170881256f);
    p = fmaf(x, p, 0.0308918810f);
    p = fmaf(x, p, -0.0501743046f);
    p = fmaf(x, p, 0.0889789874f);
    p = fmaf(x, p, -0.2145988016f);
    p = fmaf(x, p, 1.5707963050f);
    return sqrtf(fmaxf(1.0f - x, 0.0f)) * p;
}

// Full slerp (direct fallback path only).
__device__ __forceinline__ float4 qslerp(float4 q0, float4 q1, float u) {
    float dot = q0.x * q1.x + q0.y * q1.y + q0.z * q1.z + q0.w * q1.w;
    dot = fminf(fmaxf(dot, -1.0f), 1.0f);
    float sgn = (dot < 0.0f) ? -1.0f : 1.0f;
    float ad = fminf(fabsf(dot), 1.0f);
    float theta = acosf(ad);
    float st = __sinf(theta);
    float w0, w1;
    if (fabsf(st) > 1e-6f) {
        float inv = __frcp_rn(st);
        w0 = __sinf((1.0f - u) * theta) * inv;
        w1 = __sinf(u * theta) * inv;
    } else {
        w0 = 1.0f - u;
        w1 = u;
    }
    w1 *= sgn;
    return make_float4(w0 * q0.x + w1 * q1.x,
                       w0 * q0.y + w1 * q1.y,
                       w0 * q0.z + w1 * q1.z,
                       w0 * q0.w + w1 * q1.w);
}

// ---------------------------------------------------------------------------
// Precompute: one 128B record per interval, written coalesced via smem.
// ---------------------------------------------------------------------------
#define ROWF 33
__global__ __launch_bounds__(TPB)
void precompute_intervals(const float* __restrict__ trans,
                          const float* __restrict__ quats,
                          int K)
{
    __shared__ float s[WARPS * 32 * ROWF];
    int lane = threadIdx.x & 31;
    int wid = threadIdx.x >> 5;
    float* ws = s + wid * 32 * ROWF;
    int nIv = K - 1;
    int base = (blockIdx.x * WARPS + wid) * 32;
    if (base >= nIv) return;

    int i = min(base + lane, nIv - 1);     // clamp; extra rows never stored
    {
        int im1 = max(i - 1, 0);
        int ip2 = min(i + 2, K - 1);
        float p0x = trans[3*i+0], p0y = trans[3*i+1], p0z = trans[3*i+2];
        float p1x = trans[3*(i+1)+0], p1y = trans[3*(i+1)+1], p1z = trans[3*(i+1)+2];
        float pmx = trans[3*im1+0], pmy = trans[3*im1+1], pmz = trans[3*im1+2];
        float ppx = trans[3*ip2+0], ppy = trans[3*ip2+1], ppz = trans[3*ip2+2];

        float d01x = p1x - p0x, d01y = p1y - p0y, d01z = p1z - p0z;
        float m0x, m0y, m0z, m1x, m1y, m1z;
        if (i > 0) { m0x = 0.5f*(p1x - pmx); m0y = 0.5f*(p1y - pmy); m0z = 0.5f*(p1z - pmz); }
        else       { m0x = d01x; m0y = d01y; m0z = d01z; }
        if (i + 1 < K - 1) { m1x = 0.5f*(ppx - p0x); m1y = 0.5f*(ppy - p0y); m1z = 0.5f*(ppz - p0z); }
        else               { m1x = d01x; m1y = d01y; m1z = d01z; }

        const float4* q4 = (const float4*)quats;
        float4 qi  = qnormalize(q4[i]);
        float4 qi1 = qnormalize(q4[i + 1]);
        float4 qm  = qnormalize(q4[im1]);
        float4 qp  = qnormalize(q4[ip2]);

        float dm = qi.x*qi1.x + qi.y*qi1.y + qi.z*qi1.z + qi.w*qi1.w;
        dm = fminf(fmaxf(dm, -1.0f), 1.0f);
        float sgnm = (dm < 0.0f) ? -1.0f : 1.0f;
        float thm = acosf(fminf(fabsf(dm), 1.0f));
        float stm = __sinf(thm);
        float ism = (fabsf(stm) > 1e-6f) ? __frcp_rn(stm) : 0.0f;
        float4 qi1a = make_float4(sgnm*qi1.x, sgnm*qi1.y, sgnm*qi1.z, sgnm*qi1.w);

        float da = qm.x*qp.x + qm.y*qp.y + qm.z*qp.z + qm.w*qp.w;
        da = fminf(fmaxf(da, -1.0f), 1.0f);
        float sgna = (da < 0.0f) ? -1.0f : 1.0f;
        float tha = acosf(fminf(fabsf(da), 1.0f));
        float sta = __sinf(tha);
        float isa = (fabsf(sta) > 1e-6f) ? __frcp_rn(sta) : 0.0f;
        float4 qpa = make_float4(sgna*qp.x, sgna*qp.y, sgna*qp.z, sgna*qp.w);

        float* row = ws + lane * ROWF;
        row[0]=p0x;  row[1]=p0y;  row[2]=p0z;  row[3]=m0x;
        row[4]=m0y;  row[5]=m0z;  row[6]=p1x;  row[7]=p1y;
        row[8]=p1z;  row[9]=m1x;  row[10]=m1y; row[11]=m1z;
        row[12]=qi.x;  row[13]=qi.y;  row[14]=qi.z;  row[15]=qi.w;
        row[16]=qi1a.x; row[17]=qi1a.y; row[18]=qi1a.z; row[19]=qi1a.w;
        row[20]=thm;  row[21]=ism;  row[22]=tha;  row[23]=isa;
        row[24]=qm.x;  row[25]=qm.y;  row[26]=qm.z;  row[27]=qm.w;
        row[28]=qpa.x; row[29]=qpa.y; row[30]=qpa.z; row[31]=qpa.w;
    }
    __syncwarp();

    int r = lane & 7;
    int dq = lane >> 3;
    #pragma unroll
    for (int step = 0; step < 8; ++step) {
        int q = step * 4 + dq;
        int gi = base + q;
        if (gi < nIv) {
            const float* src = ws + q * ROWF + r * 4;
            g_rec[(size_t)gi * 8 + r] = make_float4(src[0], src[1], src[2], src[3]);
        }
    }
}

// ---------------------------------------------------------------------------
// Per-query math from a staged record (reads 8 conflict-free LDS.128).
// ---------------------------------------------------------------------------
struct PoseOut { float R[9]; float Tx, Ty, Tz; };

__device__ __forceinline__ void eval_pose(const float4* ws4, int lane, float u,
                                          PoseOut& o)
{
    int q7 = lane & 7;
    float4 P0 = ws4[lane * 8 + (0 ^ q7)];
    float4 P1 = ws4[lane * 8 + (1 ^ q7)];
    float4 P2 = ws4[lane * 8 + (2 ^ q7)];
    float4 P3 = ws4[lane * 8 + (3 ^ q7)];
    float4 P4 = ws4[lane * 8 + (4 ^ q7)];
    float4 P5 = ws4[lane * 8 + (5 ^ q7)];
    float4 P6 = ws4[lane * 8 + (6 ^ q7)];
    float4 P7 = ws4[lane * 8 + (7 ^ q7)];

    float u2 = u * u;
    float u3 = u2 * u;
    float h00 = 2.0f * u3 - 3.0f * u2 + 1.0f;
    float h10 = u3 - 2.0f * u2 + u;
    float h01 = -2.0f * u3 + 3.0f * u2;
    float h11 = u3 - u2;

    o.Tx = h00 * P0.x + h10 * P0.w + h01 * P1.z + h11 * P2.y;
    o.Ty = h00 * P0.y + h10 * P1.x + h01 * P1.w + h11 * P2.z;
    o.Tz = h00 * P0.z + h10 * P1.y + h01 * P2.x + h11 * P2.w;

    float thm = P5.x, ism = P5.y, tha = P5.z, isa = P5.w;
    float w0m, w1m;
    if (ism != 0.0f) {
        w0m = __sinf((1.0f - u) * thm) * ism;
        w1m = __sinf(u * thm) * ism;
    } else {
        w0m = 1.0f - u;
        w1m = u;
    }
    float4 s_main = make_float4(w0m * P3.x + w1m * P4.x,
                                w0m * P3.y + w1m * P4.y,
                                w0m * P3.z + w1m * P4.z,
                                w0m * P3.w + w1m * P4.w);
    float w0a, w1a;
    if (isa != 0.0f) {
        w0a = __sinf((1.0f - u) * tha) * isa;
        w1a = __sinf(u * tha) * isa;
    } else {
        w0a = 1.0f - u;
        w1a = u;
    }
    float4 s_aux = make_float4(w0a * P6.x + w1a * P7.x,
                               w0a * P6.y + w1a * P7.y,
                               w0a * P6.z + w1a * P7.z,
                               w0a * P6.w + w1a * P7.w);

    float v = 2.0f * u * (1.0f - u);
    float dotb = s_main.x*s_aux.x + s_main.y*s_aux.y + s_main.z*s_aux.z + s_main.w*s_aux.w;
    dotb = fminf(fmaxf(dotb, -1.0f), 1.0f);
    float sgnb = (dotb < 0.0f) ? -1.0f : 1.0f;
    float adb = fminf(fabsf(dotb), 1.0f);
    float thb = facos01(adb);
    float stb = __sinf(thb);
    float w0b, w1b;
    if (fabsf(stb) > 1e-6f) {
        float inv = __frcp_rn(stb);
        w0b = __sinf((1.0f - v) * thb) * inv;
        w1b = __sinf(v * thb) * inv;
    } else {
        w0b = 1.0f - v;
        w1b = v;
    }
    w1b *= sgnb;
    float4 q = qnormalize(make_float4(w0b * s_main.x + w1b * s_aux.x,
                                      w0b * s_main.y + w1b * s_aux.y,
                                      w0b * s_main.z + w1b * s_aux.z,
                                      w0b * s_main.w + w1b * s_aux.w));

    float w = q.x, x = q.y, y = q.z, z = q.w;
    float xx = x * x, yy = y * y, zz = z * z;
    float xy = x * y, xz = x * z, yz = y * z;
    float wx = w * x, wy = w * y, wz = w * z;
    o.R[0] = 1.0f - 2.0f * (yy + zz);
    o.R[1] = 2.0f * (xy - wz);
    o.R[2] = 2.0f * (xz + wy);
    o.R[3] = 2.0f * (xy + wz);
    o.R[4] = 1.0f - 2.0f * (xx + zz);
    o.R[5] = 2.0f * (yz - wx);
    o.R[6] = 2.0f * (xz - wy);
    o.R[7] = 2.0f * (yz + wx);
    o.R[8] = 1.0f - 2.0f * (xx + yy);
}

// Issue cp.async gather for one 32-query chunk into the given buffer.
// Returns this lane's u (interpolation parameter).
__device__ __forceinline__ float issue_chunk(const float* __restrict__ t,
                                             float4* buf, int chunk,
                                             int M, int K,
                                             float km1, float rcp,
                                             int lane, int r, int dq)
{
    int m = chunk * 32 + lane;
    float tv = (m < M) ? t[m] : 0.0f;
    // Match XLA rounding EXACTLY: t_ctrl = fl( fl(t*(K-1)) * fl(1/(N-1)) )
    float tc = __fmul_rn(__fmul_rn(tv, km1), rcp);
    int i = min(max((int)floorf(tc), 0), K - 2);
    float u = tc - (float)i;

    #pragma unroll
    for (int step = 0; step < 8; ++step) {
        int q = step * 4 + dq;
        int idx = __shfl_sync(0xffffffffu, i, q);
        const float4* src = &g_rec[(size_t)idx * 8 + r];
        uint32_t dst = (uint32_t)__cvta_generic_to_shared(&buf[q * 8 + (r ^ (q & 7))]);
        CP_ASYNC16(dst, src);
    }
    CP_ASYNC_COMMIT();
    return u;
}

// ---------------------------------------------------------------------------
// Main kernel: persistent warps, cp.async double-buffered chunks of 32.
// ---------------------------------------------------------------------------
__global__ __launch_bounds__(TPB)
void camera_spline_kernel(const float* __restrict__ t,
                          const int* __restrict__ Nptr,
                          float* __restrict__ out,
                          int M, int K, int nChunks)
{
    __shared__ float4 s4[WARPS * 512];     // 2 x 4KB buffers per warp
    int lane = threadIdx.x & 31;
    int wid = threadIdx.x >> 5;
    float4* buf0 = s4 + wid * 512;
    float4* buf1 = buf0 + 256;

    int warpId = blockIdx.x * WARPS + wid;
    int totalWarps = gridDim.x * WARPS;

    int N = __ldg(Nptr);
    float km1 = (float)(K - 1);
    float nm1 = (float)max(N - 1, 1);
    float rcp = __fdiv_rn(1.0f, nm1);

    int r = lane & 7;
    int dq = lane >> 3;

    // prologue: prefetch up to 2 chunks
    float u_pend[2] = {0.0f, 0.0f};
    if (warpId < nChunks)
        u_pend[0] = issue_chunk(t, buf0, warpId, M, K, km1, rcp, lane, r, dq);
    if (warpId + totalWarps < nChunks)
        u_pend[1] = issue_chunk(t, buf1, warpId + totalWarps, M, K, km1, rcp, lane, r, dq);

    int jb = 0;
    for (int c = warpId; c < nChunks; c += totalWarps, jb ^= 1) {
        float4* buf = jb ? buf1 : buf0;
        float* wsf = (float*)buf;
        bool hasNext = (c + totalWarps) < nChunks;

        if (hasNext) { CP_ASYNC_WAIT(1); } else { CP_ASYNC_WAIT(0); }
        __syncwarp();

        PoseOut o;
        eval_pose(buf, lane, u_pend[jb], o);
        __syncwarp();                      // all record reads complete

        int base = c * 32;
        int count = min(32, M - base);

        // stage outputs into the (now dead) record buffer:
        // R at q*9+c (9 coprime 32), T at 288+q*3+c
        if (base + lane < M) {
            float* rr = wsf + lane * 9;
            #pragma unroll
            for (int cc = 0; cc < 9; ++cc) rr[cc] = o.R[cc];
            float* tt = wsf + 288 + lane * 3;
            tt[0] = o.Tx; tt[1] = o.Ty; tt[2] = o.Tz;
        }
        __syncwarp();

        // coalesced writeback (evict-first)
        if (count == 32) {
            size_t rBase = (size_t)base * 9;
            size_t tBase = (size_t)M * 9 + (size_t)base * 3;
            if (((rBase & 3) == 0) && ((tBase & 3) == 0)) {
                float4* dstR = (float4*)(out + rBase);
                const float4* srcR = (const float4*)wsf;
                #pragma unroll
                for (int n = lane; n < 72; n += 32)
                    __stcs(dstR + n, srcR[n]);
                float4* dstT = (float4*)(out + tBase);
                const float4* srcT = (const float4*)(wsf + 288);
                if (lane < 24)
                    __stcs(dstT + lane, srcT[lane]);
            } else {
                float* dstR = out + rBase;
                for (int e = lane; e < 288; e += 32) dstR[e] = wsf[e];
                float* dstT = out + tBase;
                for (int e = lane; e < 96; e += 32) dstT[e] = wsf[288 + e];
            }
        } else if (count > 0) {
            float* dstR = out + (size_t)base * 9;
            for (int e = lane; e < count * 9; e += 32) dstR[e] = wsf[e];
            float* dstT = out + (size_t)M * 9 + (size_t)base * 3;
            for (int e = lane; e < count * 3; e += 32) dstT[e] = wsf[288 + e];
        }
        __syncwarp();                      // writeback reads done; buffer reusable

        // prefetch chunk c + 2*stride into this buffer
        int cn2 = c + 2 * totalWarps;
        if (cn2 < nChunks)
            u_pend[jb] = issue_chunk(t, buf, cn2, M, K, km1, rcp, lane, r, dq);
    }
}

// ---------------------------------------------------------------------------
// Fallback for K-1 > CAPI: direct gather.
// ---------------------------------------------------------------------------
__global__ __launch_bounds__(256)
void camera_spline_kernel_direct(const float* __restrict__ t,
                                 const float* __restrict__ ctrl_trans,
                                 const float* __restrict__ ctrl_quats,
                                 const int* __restrict__ Nptr,
                                 float* __restrict__ out,
                                 int M, int K)
{
    int m = blockIdx.x * blockDim.x + threadIdx.x;
    if (m >= M) return;

    int N = __ldg(Nptr);
    float km1 = (float)(K - 1);
    float nm1 = (float)max(N - 1, 1);
    float rcp = __fdiv_rn(1.0f, nm1);
    float tc = __fmul_rn(__fmul_rn(t[m], km1), rcp);
    int i = min(max((int)floorf(tc), 0), K - 2);
    float u = tc - (float)i;
    int im1 = max(i - 1, 0);
    int ip2 = min(i + 2, K - 1);

    float3 p0 = make_float3(ctrl_trans[3*i+0], ctrl_trans[3*i+1], ctrl_trans[3*i+2]);
    float3 p1 = make_float3(ctrl_trans[3*(i+1)+0], ctrl_trans[3*(i+1)+1], ctrl_trans[3*(i+1)+2]);
    float3 pm = make_float3(ctrl_trans[3*im1+0], ctrl_trans[3*im1+1], ctrl_trans[3*im1+2]);
    float3 pp = make_float3(ctrl_trans[3*ip2+0], ctrl_trans[3*ip2+1], ctrl_trans[3*ip2+2]);

    float3 d01 = make_float3(p1.x - p0.x, p1.y - p0.y, p1.z - p0.z);
    float3 m0 = (i > 0) ? make_float3(0.5f*(p1.x-pm.x), 0.5f*(p1.y-pm.y), 0.5f*(p1.z-pm.z)) : d01;
    float3 m1 = (i + 1 < K - 1) ? make_float3(0.5f*(pp.x-p0.x), 0.5f*(pp.y-p0.y), 0.5f*(pp.z-p0.z)) : d01;

    float u2 = u * u, u3 = u2 * u;
    float h00 = 2.0f*u3 - 3.0f*u2 + 1.0f;
    float h10 = u3 - 2.0f*u2 + u;
    float h01 = -2.0f*u3 + 3.0f*u2;
    float h11 = u3 - u2;
    float Tx = h00*p0.x + h10*m0.x + h01*p1.x + h11*m1.x;
    float Ty = h00*p0.y + h10*m0.y + h01*p1.y + h11*m1.y;
    float Tz = h00*p0.z + h10*m0.z + h01*p1.z + h11*m1.z;

    const float4* quats = (const float4*)ctrl_quats;
    float4 q_i  = qnormalize(quats[i]);
    float4 q_i1 = qnormalize(quats[i + 1]);
    float4 q_m  = qnormalize(quats[im1]);
    float4 q_p  = qnormalize(quats[ip2]);
    float4 s_main = qslerp(q_i, q_i1, u);
    float4 s_aux  = qslerp(q_m, q_p, u);
    float4 q = qnormalize(qslerp(s_main, s_aux, 2.0f * u * (1.0f - u)));

    float w = q.x, x = q.y, y = q.z, z = q.w;
    float* R = out + (size_t)m * 9;
    R[0] = 1.0f - 2.0f * (y*y + z*z);
    R[1] = 2.0f * (x*y - w*z);
    R[2] = 2.0f * (x*z + w*y);
    R[3] = 2.0f * (x*y + w*z);
    R[4] = 1.0f - 2.0f * (x*x + z*z);
    R[5] = 2.0f * (y*z - w*x);
    R[6] = 2.0f * (x*z - w*y);
    R[7] = 2.0f * (y*z + w*x);
    R[8] = 1.0f - 2.0f * (x*x + y*y);
    float* Tout = out + (size_t)M * 9 + (size_t)m * 3;
    Tout[0] = Tx; Tout[1] = Ty; Tout[2] = Tz;
}

extern "C" void kernel_launch(void* const* d_in, const int* in_sizes, int n_in,
                              void* d_out, int out_size)
{
    const float* t          = (const float*)d_in[0];
    const float* ctrl_trans = (const float*)d_in[1];
    const float* ctrl_quats = (const float*)d_in[2];
    const int*   Nptr       = (const int*)d_in[3];

    int M = in_sizes[0];
    int K = in_sizes[1] / 3;

    float* out = (float*)d_out;

    if (K - 1 <= CAPI) {
        int nIv = K - 1;
        int pblocks = (nIv + TPB - 1) / TPB;
        precompute_intervals<<<pblocks, TPB>>>(ctrl_trans, ctrl_quats, K);

        int nChunks = (M + 31) / 32;
        int blocks = 7 * 148;                       // ~7 blocks per SM (smem-limited)
        int maxBlocks = (nChunks + WARPS - 1) / WARPS;
        if (blocks > maxBlocks) blocks = maxBlocks;
        camera_spline_kernel<<<blocks, TPB>>>(t, Nptr, out, M, K, nChunks);
    } else {
        int blocks = (M + 255) / 256;
        camera_spline_kernel_direct<<<blocks, 256>>>(t, ctrl_trans, ctrl_quats, Nptr, out, M, K);
    }
}

// round 12
// speedup vs baseline: 1.0703x; 1.0703x over previous
#include <cuda_runtime.h>
#include <cuda_bf16.h>
#include <cstdint>

// CameraSpline pose evaluation.
// Inputs (metadata order): t [M] f32, ctrl_trans [K,3] f32, ctrl_quats [K,4] f32, N [1] i32.
// Output: R [M,3,3] flattened (9*M floats) followed by T [M,3] (3*M floats).
//
// R11 -> R12: back to the R10 shape (2 queries/thread) but each 8-load batch
// is staged to smem IMMEDIATELY (load A, STS A, load B, STS B, one syncwarp,
// compute A, compute B). Peak data regs ~32 vs R10's 64 (96 total, occ 27.8%).
// Cross-warp occupancy, not in-warp MLP, now hides the gather latency.

#define TPB 128
#define WARPS (TPB / 32)
#define QPW 64                     // queries per warp
#define CAPI 524288                // max intervals in the record table

// One 128B record (8 float4 parts) per interval i:
//  p0: p0x p0y p0z m0x | p1: m0y m0z p1x p1y | p2: p1z m1x m1y m1z
//  p3: q_i | p4: q_i1_adj (sign folded) | p5: thm ism tha isa
//  p6: q_im1 | p7: q_ip2_adj (sign folded)
__device__ __align__(128) float4 g_rec[(size_t)CAPI * 8];

__device__ __forceinline__ float4 qnormalize(float4 q) {
    float inv = rsqrtf(q.x * q.x + q.y * q.y + q.z * q.z + q.w * q.w);
    return make_float4(q.x * inv, q.y * inv, q.z * inv, q.w * inv);
}

// acos(x) for x in [0,1]: sqrt(1-x) * poly7 (Hastings; |err| ~ 2e-8).
__device__ __forceinline__ float facos01(float x) {
    float p = fmaf(x, -0.0012624911f, 0.0066700901f);
    p = fmaf(x, p, -0.0170881256f);
    p = fmaf(x, p, 0.0308918810f);
    p = fmaf(x, p, -0.0501743046f);
    p = fmaf(x, p, 0.0889789874f);
    p = fmaf(x, p, -0.2145988016f);
    p = fmaf(x, p, 1.5707963050f);
    return sqrtf(fmaxf(1.0f - x, 0.0f)) * p;
}

// Full slerp (direct fallback path only).
__device__ __forceinline__ float4 qslerp(float4 q0, float4 q1, float u) {
    float dot = q0.x * q1.x + q0.y * q1.y + q0.z * q1.z + q0.w * q1.w;
    dot = fminf(fmaxf(dot, -1.0f), 1.0f);
    float sgn = (dot < 0.0f) ? -1.0f : 1.0f;
    float ad = fminf(fabsf(dot), 1.0f);
    float theta = acosf(ad);
    float st = __sinf(theta);
    float w0, w1;
    if (fabsf(st) > 1e-6f) {
        float inv = __frcp_rn(st);
        w0 = __sinf((1.0f - u) * theta) * inv;
        w1 = __sinf(u * theta) * inv;
    } else {
        w0 = 1.0f - u;
        w1 = u;
    }
    w1 *= sgn;
    return make_float4(w0 * q0.x + w1 * q1.x,
                       w0 * q0.y + w1 * q1.y,
                       w0 * q0.z + w1 * q1.z,
                       w0 * q0.w + w1 * q1.w);
}

// ---------------------------------------------------------------------------
// Precompute: one 128B record per interval, written coalesced via smem.
// ---------------------------------------------------------------------------
#define ROWF 33
__global__ __launch_bounds__(TPB)
void precompute_intervals(const float* __restrict__ trans,
                          const float* __restrict__ quats,
                          int K)
{
    __shared__ float s[WARPS * 32 * ROWF];
    int lane = threadIdx.x & 31;
    int wid = threadIdx.x >> 5;
    float* ws = s + wid * 32 * ROWF;
    int nIv = K - 1;
    int base = (blockIdx.x * WARPS + wid) * 32;
    if (base >= nIv) return;

    int i = min(base + lane, nIv - 1);     // clamp; extra rows never stored
    {
        int im1 = max(i - 1, 0);
        int ip2 = min(i + 2, K - 1);
        float p0x = trans[3*i+0], p0y = trans[3*i+1], p0z = trans[3*i+2];
        float p1x = trans[3*(i+1)+0], p1y = trans[3*(i+1)+1], p1z = trans[3*(i+1)+2];
        float pmx = trans[3*im1+0], pmy = trans[3*im1+1], pmz = trans[3*im1+2];
        float ppx = trans[3*ip2+0], ppy = trans[3*ip2+1], ppz = trans[3*ip2+2];

        float d01x = p1x - p0x, d01y = p1y - p0y, d01z = p1z - p0z;
        float m0x, m0y, m0z, m1x, m1y, m1z;
        if (i > 0) { m0x = 0.5f*(p1x - pmx); m0y = 0.5f*(p1y - pmy); m0z = 0.5f*(p1z - pmz); }
        else       { m0x = d01x; m0y = d01y; m0z = d01z; }
        if (i + 1 < K - 1) { m1x = 0.5f*(ppx - p0x); m1y = 0.5f*(ppy - p0y); m1z = 0.5f*(ppz - p0z); }
        else               { m1x = d01x; m1y = d01y; m1z = d01z; }

        const float4* q4 = (const float4*)quats;
        float4 qi  = qnormalize(q4[i]);
        float4 qi1 = qnormalize(q4[i + 1]);
        float4 qm  = qnormalize(q4[im1]);
        float4 qp  = qnormalize(q4[ip2]);

        float dm = qi.x*qi1.x + qi.y*qi1.y + qi.z*qi1.z + qi.w*qi1.w;
        dm = fminf(fmaxf(dm, -1.0f), 1.0f);
        float sgnm = (dm < 0.0f) ? -1.0f : 1.0f;
        float thm = acosf(fminf(fabsf(dm), 1.0f));
        float stm = __sinf(thm);
        float ism = (fabsf(stm) > 1e-6f) ? __frcp_rn(stm) : 0.0f;
        float4 qi1a = make_float4(sgnm*qi1.x, sgnm*qi1.y, sgnm*qi1.z, sgnm*qi1.w);

        float da = qm.x*qp.x + qm.y*qp.y + qm.z*qp.z + qm.w*qp.w;
        da = fminf(fmaxf(da, -1.0f), 1.0f);
        float sgna = (da < 0.0f) ? -1.0f : 1.0f;
        float tha = acosf(fminf(fabsf(da), 1.0f));
        float sta = __sinf(tha);
        float isa = (fabsf(sta) > 1e-6f) ? __frcp_rn(sta) : 0.0f;
        float4 qpa = make_float4(sgna*qp.x, sgna*qp.y, sgna*qp.z, sgna*qp.w);

        float* row = ws + lane * ROWF;
        row[0]=p0x;  row[1]=p0y;  row[2]=p0z;  row[3]=m0x;
        row[4]=m0y;  row[5]=m0z;  row[6]=p1x;  row[7]=p1y;
        row[8]=p1z;  row[9]=m1x;  row[10]=m1y; row[11]=m1z;
        row[12]=qi.x;  row[13]=qi.y;  row[14]=qi.z;  row[15]=qi.w;
        row[16]=qi1a.x; row[17]=qi1a.y; row[18]=qi1a.z; row[19]=qi1a.w;
        row[20]=thm;  row[21]=ism;  row[22]=tha;  row[23]=isa;
        row[24]=qm.x;  row[25]=qm.y;  row[26]=qm.z;  row[27]=qm.w;
        row[28]=qpa.x; row[29]=qpa.y; row[30]=qpa.z; row[31]=qpa.w;
    }
    __syncwarp();

    int r = lane & 7;
    int dq = lane >> 3;
    #pragma unroll
    for (int step = 0; step < 8; ++step) {
        int q = step * 4 + dq;
        int gi = base + q;
        if (gi < nIv) {
            const float* src = ws + q * ROWF + r * 4;
            g_rec[(size_t)gi * 8 + r] = make_float4(src[0], src[1], src[2], src[3]);
        }
    }
}

// ---------------------------------------------------------------------------
// Per-query math from a staged record (8 conflict-free LDS.128).
// ---------------------------------------------------------------------------
struct PoseOut { float R[9]; float Tx, Ty, Tz; };

__device__ __forceinline__ void eval_pose(const float4* ws4, int lane, float u,
                                          PoseOut& o)
{
    int q7 = lane & 7;
    float4 P0 = ws4[lane * 8 + (0 ^ q7)];
    float4 P1 = ws4[lane * 8 + (1 ^ q7)];
    float4 P2 = ws4[lane * 8 + (2 ^ q7)];
    float4 P3 = ws4[lane * 8 + (3 ^ q7)];
    float4 P4 = ws4[lane * 8 + (4 ^ q7)];
    float4 P5 = ws4[lane * 8 + (5 ^ q7)];
    float4 P6 = ws4[lane * 8 + (6 ^ q7)];
    float4 P7 = ws4[lane * 8 + (7 ^ q7)];

    float u2 = u * u;
    float u3 = u2 * u;
    float h00 = 2.0f * u3 - 3.0f * u2 + 1.0f;
    float h10 = u3 - 2.0f * u2 + u;
    float h01 = -2.0f * u3 + 3.0f * u2;
    float h11 = u3 - u2;

    o.Tx = h00 * P0.x + h10 * P0.w + h01 * P1.z + h11 * P2.y;
    o.Ty = h00 * P0.y + h10 * P1.x + h01 * P1.w + h11 * P2.z;
    o.Tz = h00 * P0.z + h10 * P1.y + h01 * P2.x + h11 * P2.w;

    float thm = P5.x, ism = P5.y, tha = P5.z, isa = P5.w;
    float w0m, w1m;
    if (ism != 0.0f) {
        w0m = __sinf((1.0f - u) * thm) * ism;
        w1m = __sinf(u * thm) * ism;
    } else {
        w0m = 1.0f - u;
        w1m = u;
    }
    float4 s_main = make_float4(w0m * P3.x + w1m * P4.x,
                                w0m * P3.y + w1m * P4.y,
                                w0m * P3.z + w1m * P4.z,
                                w0m * P3.w + w1m * P4.w);
    float w0a, w1a;
    if (isa != 0.0f) {
        w0a = __sinf((1.0f - u) * tha) * isa;
        w1a = __sinf(u * tha) * isa;
    } else {
        w0a = 1.0f - u;
        w1a = u;
    }
    float4 s_aux = make_float4(w0a * P6.x + w1a * P7.x,
                               w0a * P6.y + w1a * P7.y,
                               w0a * P6.z + w1a * P7.z,
                               w0a * P6.w + w1a * P7.w);

    float v = 2.0f * u * (1.0f - u);
    float dotb = s_main.x*s_aux.x + s_main.y*s_aux.y + s_main.z*s_aux.z + s_main.w*s_aux.w;
    dotb = fminf(fmaxf(dotb, -1.0f), 1.0f);
    float sgnb = (dotb < 0.0f) ? -1.0f : 1.0f;
    float adb = fminf(fabsf(dotb), 1.0f);
    float thb = facos01(adb);
    float stb = __sinf(thb);
    float w0b, w1b;
    if (fabsf(stb) > 1e-6f) {
        float inv = __frcp_rn(stb);
        w0b = __sinf((1.0f - v) * thb) * inv;
        w1b = __sinf(v * thb) * inv;
    } else {
        w0b = 1.0f - v;
        w1b = v;
    }
    w1b *= sgnb;
    float4 q = qnormalize(make_float4(w0b * s_main.x + w1b * s_aux.x,
                                      w0b * s_main.y + w1b * s_aux.y,
                                      w0b * s_main.z + w1b * s_aux.z,
                                      w0b * s_main.w + w1b * s_aux.w));

    float w = q.x, x = q.y, y = q.z, z = q.w;
    float xx = x * x, yy = y * y, zz = z * z;
    float xy = x * y, xz = x * z, yz = y * z;
    float wx = w * x, wy = w * y, wz = w * z;
    o.R[0] = 1.0f - 2.0f * (yy + zz);
    o.R[1] = 2.0f * (xy - wz);
    o.R[2] = 2.0f * (xz + wy);
    o.R[3] = 2.0f * (xy + wz);
    o.R[4] = 1.0f - 2.0f * (xx + zz);
    o.R[5] = 2.0f * (yz - wx);
    o.R[6] = 2.0f * (xz - wy);
    o.R[7] = 2.0f * (yz + wx);
    o.R[8] = 1.0f - 2.0f * (xx + yy);
}

// Cooperative gather of one 32-query chunk into buf (load -> STS immediately).
__device__ __forceinline__ void gather_chunk(float4* buf, int i, int r, int dq)
{
    float4 v[8];
    #pragma unroll
    for (int step = 0; step < 8; ++step) {
        int q = step * 4 + dq;
        int idx = __shfl_sync(0xffffffffu, i, q);
        v[step] = g_rec[(size_t)idx * 8 + r];
    }
    #pragma unroll
    for (int step = 0; step < 8; ++step) {
        int q = step * 4 + dq;
        buf[q * 8 + (r ^ (q & 7))] = v[step];
    }
}

// ---------------------------------------------------------------------------
// Main kernel: 2 queries/thread, two 4KB buffers/warp, low reg pressure.
// ---------------------------------------------------------------------------
__global__ __launch_bounds__(TPB)
void camera_spline_kernel(const float* __restrict__ t,
                          const int* __restrict__ Nptr,
                          float* __restrict__ out,
                          int M, int K)
{
    __shared__ float4 s4[WARPS * 512];     // 2 x 4KB per warp
    int lane = threadIdx.x & 31;
    int wid = threadIdx.x >> 5;
    float4* bufA = s4 + wid * 512;
    float4* bufB = bufA + 256;
    float* fA = (float*)bufA;
    float* fB = (float*)bufB;
    int warpBase = (blockIdx.x * WARPS + wid) * QPW;
    int m0 = warpBase + lane;
    int m1 = warpBase + 32 + lane;

    int N = __ldg(Nptr);
    float km1 = (float)(K - 1);
    float nm1 = (float)max(N - 1, 1);
    // Match XLA rounding EXACTLY: t_ctrl = fl( fl(t*(K-1)) * fl(1/(N-1)) )
    float rcp = __fdiv_rn(1.0f, nm1);
    float tv0 = (m0 < M) ? t[m0] : 0.0f;
    float tv1 = (m1 < M) ? t[m1] : 0.0f;
    float tc0 = __fmul_rn(__fmul_rn(tv0, km1), rcp);
    float tc1 = __fmul_rn(__fmul_rn(tv1, km1), rcp);
    int i0 = min(max((int)floorf(tc0), 0), K - 2);
    int i1 = min(max((int)floorf(tc1), 0), K - 2);
    float u0 = tc0 - (float)i0;
    float u1 = tc1 - (float)i1;

    int r = lane & 7;
    int dq = lane >> 3;

    // gather A then B; A's registers die at its STS, so peak data regs ~32
    gather_chunk(bufA, i0, r, dq);
    gather_chunk(bufB, i1, r, dq);
    __syncwarp();

    PoseOut o0, o1;
    eval_pose(bufA, lane, u0, o0);
    __syncwarp();                  // bufA record reads complete (all lanes)

    // stage o0.R into bufA (records dead); o0.T stays in regs until B done
    if (m0 < M) {
        float* rr = fA + lane * 9;
        #pragma unroll
        for (int c = 0; c < 9; ++c) rr[c] = o0.R[c];
    }

    eval_pose(bufB, lane, u1, o1);
    __syncwarp();                  // bufB record reads complete

    // stage o1.R into bufA rows 32..63; T of both chunks into bufB
    if (m1 < M) {
        float* rr = fA + (lane + 32) * 9;
        #pragma unroll
        for (int c = 0; c < 9; ++c) rr[c] = o1.R[c];
    }
    if (m0 < M) { float* tt = fB + lane * 3;        tt[0]=o0.Tx; tt[1]=o0.Ty; tt[2]=o0.Tz; }
    if (m1 < M) { float* tt = fB + (lane + 32) * 3; tt[0]=o1.Tx; tt[1]=o1.Ty; tt[2]=o1.Tz; }
    __syncwarp();

    // ---- warp-local coalesced writeback (evict-first stores) ----
    int count = min(QPW, M - warpBase);
    if (count <= 0) return;

    if (count == QPW) {
        float4* dstR = (float4*)(out + (size_t)warpBase * 9);   // warpBase%64==0 -> aligned
        const float4* srcR = (const float4*)fA;
        #pragma unroll
        for (int n = lane; n < 144; n += 32)
            __stcs(dstR + n, srcR[n]);
        size_t tBase = (size_t)M * 9 + (size_t)warpBase * 3;
        if ((tBase & 3) == 0) {
            float4* dstT = (float4*)(out + tBase);
            const float4* srcT = (const float4*)fB;
            #pragma unroll
            for (int n = lane; n < 48; n += 32)
                __stcs(dstT + n, srcT[n]);
        } else {
            float* dstT = out + tBase;
            for (int e = lane; e < 192; e += 32)
                dstT[e] = fB[e];
        }
    } else {
        float* dstR = out + (size_t)warpBase * 9;
        for (int e = lane; e < count * 9; e += 32)
            dstR[e] = fA[e];
        float* dstT = out + (size_t)M * 9 + (size_t)warpBase * 3;
        for (int e = lane; e < count * 3; e += 32)
            dstT[e] = fB[e];
    }
}

// ---------------------------------------------------------------------------
// Fallback for K-1 > CAPI: direct gather.
// ---------------------------------------------------------------------------
__global__ __launch_bounds__(256)
void camera_spline_kernel_direct(const float* __restrict__ t,
                                 const float* __restrict__ ctrl_trans,
                                 const float* __restrict__ ctrl_quats,
                                 const int* __restrict__ Nptr,
                                 float* __restrict__ out,
                                 int M, int K)
{
    int m = blockIdx.x * blockDim.x + threadIdx.x;
    if (m >= M) return;

    int N = __ldg(Nptr);
    float km1 = (float)(K - 1);
    float nm1 = (float)max(N - 1, 1);
    float rcp = __fdiv_rn(1.0f, nm1);
    float tc = __fmul_rn(__fmul_rn(t[m], km1), rcp);
    int i = min(max((int)floorf(tc), 0), K - 2);
    float u = tc - (float)i;
    int im1 = max(i - 1, 0);
    int ip2 = min(i + 2, K - 1);

    float3 p0 = make_float3(ctrl_trans[3*i+0], ctrl_trans[3*i+1], ctrl_trans[3*i+2]);
    float3 p1 = make_float3(ctrl_trans[3*(i+1)+0], ctrl_trans[3*(i+1)+1], ctrl_trans[3*(i+1)+2]);
    float3 pm = make_float3(ctrl_trans[3*im1+0], ctrl_trans[3*im1+1], ctrl_trans[3*im1+2]);
    float3 pp = make_float3(ctrl_trans[3*ip2+0], ctrl_trans[3*ip2+1], ctrl_trans[3*ip2+2]);

    float3 d01 = make_float3(p1.x - p0.x, p1.y - p0.y, p1.z - p0.z);
    float3 m0 = (i > 0) ? make_float3(0.5f*(p1.x-pm.x), 0.5f*(p1.y-pm.y), 0.5f*(p1.z-pm.z)) : d01;
    float3 m1 = (i + 1 < K - 1) ? make_float3(0.5f*(pp.x-p0.x), 0.5f*(pp.y-p0.y), 0.5f*(pp.z-p0.z)) : d01;

    float u2 = u * u, u3 = u2 * u;
    float h00 = 2.0f*u3 - 3.0f*u2 + 1.0f;
    float h10 = u3 - 2.0f*u2 + u;
    float h01 = -2.0f*u3 + 3.0f*u2;
    float h11 = u3 - u2;
    float Tx = h00*p0.x + h10*m0.x + h01*p1.x + h11*m1.x;
    float Ty = h00*p0.y + h10*m0.y + h01*p1.y + h11*m1.y;
    float Tz = h00*p0.z + h10*m0.z + h01*p1.z + h11*m1.z;

    const float4* quats = (const float4*)ctrl_quats;
    float4 q_i  = qnormalize(quats[i]);
    float4 q_i1 = qnormalize(quats[i + 1]);
    float4 q_m  = qnormalize(quats[im1]);
    float4 q_p  = qnormalize(quats[ip2]);
    float4 s_main = qslerp(q_i, q_i1, u);
    float4 s_aux  = qslerp(q_m, q_p, u);
    float4 q = qnormalize(qslerp(s_main, s_aux, 2.0f * u * (1.0f - u)));

    float w = q.x, x = q.y, y = q.z, z = q.w;
    float* R = out + (size_t)m * 9;
    R[0] = 1.0f - 2.0f * (y*y + z*z);
    R[1] = 2.0f * (x*y - w*z);
    R[2] = 2.0f * (x*z + w*y);
    R[3] = 2.0f * (x*y + w*z);
    R[4] = 1.0f - 2.0f * (x*x + z*z);
    R[5] = 2.0f * (y*z - w*x);
    R[6] = 2.0f * (x*z - w*y);
    R[7] = 2.0f * (y*z + w*x);
    R[8] = 1.0f - 2.0f * (x*x + y*y);
    float* Tout = out + (size_t)M * 9 + (size_t)m * 3;
    Tout[0] = Tx; Tout[1] = Ty; Tout[2] = Tz;
}

extern "C" void kernel_launch(void* const* d_in, const int* in_sizes, int n_in,
                              void* d_out, int out_size)
{
    const float* t          = (const float*)d_in[0];
    const float* ctrl_trans = (const float*)d_in[1];
    const float* ctrl_quats = (const float*)d_in[2];
    const int*   Nptr       = (const int*)d_in[3];

    int M = in_sizes[0];
    int K = in_sizes[1] / 3;

    float* out = (float*)d_out;

    if (K - 1 <= CAPI) {
        int nIv = K - 1;
        int pblocks = (nIv + TPB - 1) / TPB;
        precompute_intervals<<<pblocks, TPB>>>(ctrl_trans, ctrl_quats, K);
        int qPerBlock = WARPS * QPW;
        int blocks = (M + qPerBlock - 1) / qPerBlock;
        camera_spline_kernel<<<blocks, TPB>>>(t, Nptr, out, M, K);
    } else {
        int blocks = (M + 255) / 256;
        camera_spline_kernel_direct<<<blocks, 256>>>(t, ctrl_trans, ctrl_quats, Nptr, out, M, K);
    }
}

// round 14
// speedup vs baseline: 1.1723x; 1.0953x over previous
#include <cuda_runtime.h>
#include <cuda_bf16.h>
#include <cstdint>

// CameraSpline pose evaluation.
// Inputs (metadata order): t [M] f32, ctrl_trans [K,3] f32, ctrl_quats [K,4] f32, N [1] i32.
// Output: R [M,3,3] flattened (9*M floats) followed by T [M,3] (3*M floats).
//
// R12 -> R13 (resubmitted R14; R13 bench was an infra failure):
// revert to the R9 operating point (1 query/thread, 32 regs, 16KB smem,
// occ 72%) — all 2-query variants (R10/R11/R12) lost >=10us to
// register/smem pressure. Keep R10's only pressure-free win: facos01
// (sqrt+7fma) replacing the heavyweight acosf in the blend slerp, which
// shortens the per-thread serial latency chain.

#define TPB 128
#define WARPS (TPB / 32)
#define CAPI 524288                // max intervals in the record table

// One 128B record (8 float4 parts) per interval i:
//  p0: p0x p0y p0z m0x | p1: m0y m0z p1x p1y | p2: p1z m1x m1y m1z
//  p3: q_i | p4: q_i1_adj (sign folded) | p5: thm ism tha isa
//  p6: q_im1 | p7: q_ip2_adj (sign folded)
__device__ __align__(128) float4 g_rec[(size_t)CAPI * 8];

__device__ __forceinline__ float4 qnormalize(float4 q) {
    float inv = rsqrtf(q.x * q.x + q.y * q.y + q.z * q.z + q.w * q.w);
    return make_float4(q.x * inv, q.y * inv, q.z * inv, q.w * inv);
}

// acos(x) for x in [0,1]: sqrt(1-x) * poly7 (Hastings; |err| ~ 2e-8).
__device__ __forceinline__ float facos01(float x) {
    float p = fmaf(x, -0.0012624911f, 0.0066700901f);
    p = fmaf(x, p, -0.0170881256f);
    p = fmaf(x, p, 0.0308918810f);
    p = fmaf(x, p, -0.0501743046f);
    p = fmaf(x, p, 0.0889789874f);
    p = fmaf(x, p, -0.2145988016f);
    p = fmaf(x, p, 1.5707963050f);
    return sqrtf(fmaxf(1.0f - x, 0.0f)) * p;
}

// Full slerp (direct fallback path only).
__device__ __forceinline__ float4 qslerp(float4 q0, float4 q1, float u) {
    float dot = q0.x * q1.x + q0.y * q1.y + q0.z * q1.z + q0.w * q1.w;
    dot = fminf(fmaxf(dot, -1.0f), 1.0f);
    float sgn = (dot < 0.0f) ? -1.0f : 1.0f;
    float ad = fminf(fabsf(dot), 1.0f);
    float theta = acosf(ad);
    float st = __sinf(theta);
    float w0, w1;
    if (fabsf(st) > 1e-6f) {
        float inv = __frcp_rn(st);
        w0 = __sinf((1.0f - u) * theta) * inv;
        w1 = __sinf(u * theta) * inv;
    } else {
        w0 = 1.0f - u;
        w1 = u;
    }
    w1 *= sgn;
    return make_float4(w0 * q0.x + w1 * q1.x,
                       w0 * q0.y + w1 * q1.y,
                       w0 * q0.z + w1 * q1.z,
                       w0 * q0.w + w1 * q1.w);
}

// ---------------------------------------------------------------------------
// Precompute: one 128B record per interval, written coalesced via smem.
// ---------------------------------------------------------------------------
#define ROWF 33
__global__ __launch_bounds__(TPB)
void precompute_intervals(const float* __restrict__ trans,
                          const float* __restrict__ quats,
                          int K)
{
    __shared__ float s[WARPS * 32 * ROWF];
    int lane = threadIdx.x & 31;
    int wid = threadIdx.x >> 5;
    float* ws = s + wid * 32 * ROWF;
    int nIv = K - 1;
    int base = (blockIdx.x * WARPS + wid) * 32;
    if (base >= nIv) return;

    int i = min(base + lane, nIv - 1);     // clamp; extra rows never stored
    {
        int im1 = max(i - 1, 0);
        int ip2 = min(i + 2, K - 1);
        float p0x = trans[3*i+0], p0y = trans[3*i+1], p0z = trans[3*i+2];
        float p1x = trans[3*(i+1)+0], p1y = trans[3*(i+1)+1], p1z = trans[3*(i+1)+2];
        float pmx = trans[3*im1+0], pmy = trans[3*im1+1], pmz = trans[3*im1+2];
        float ppx = trans[3*ip2+0], ppy = trans[3*ip2+1], ppz = trans[3*ip2+2];

        float d01x = p1x - p0x, d01y = p1y - p0y, d01z = p1z - p0z;
        float m0x, m0y, m0z, m1x, m1y, m1z;
        if (i > 0) { m0x = 0.5f*(p1x - pmx); m0y = 0.5f*(p1y - pmy); m0z = 0.5f*(p1z - pmz); }
        else       { m0x = d01x; m0y = d01y; m0z = d01z; }
        if (i + 1 < K - 1) { m1x = 0.5f*(ppx - p0x); m1y = 0.5f*(ppy - p0y); m1z = 0.5f*(ppz - p0z); }
        else               { m1x = d01x; m1y = d01y; m1z = d01z; }

        const float4* q4 = (const float4*)quats;
        float4 qi  = qnormalize(q4[i]);
        float4 qi1 = qnormalize(q4[i + 1]);
        float4 qm  = qnormalize(q4[im1]);
        float4 qp  = qnormalize(q4[ip2]);

        float dm = qi.x*qi1.x + qi.y*qi1.y + qi.z*qi1.z + qi.w*qi1.w;
        dm = fminf(fmaxf(dm, -1.0f), 1.0f);
        float sgnm = (dm < 0.0f) ? -1.0f : 1.0f;
        float thm = acosf(fminf(fabsf(dm), 1.0f));
        float stm = __sinf(thm);
        float ism = (fabsf(stm) > 1e-6f) ? __frcp_rn(stm) : 0.0f;
        float4 qi1a = make_float4(sgnm*qi1.x, sgnm*qi1.y, sgnm*qi1.z, sgnm*qi1.w);

        float da = qm.x*qp.x + qm.y*qp.y + qm.z*qp.z + qm.w*qp.w;
        da = fminf(fmaxf(da, -1.0f), 1.0f);
        float sgna = (da < 0.0f) ? -1.0f : 1.0f;
        float tha = acosf(fminf(fabsf(da), 1.0f));
        float sta = __sinf(tha);
        float isa = (fabsf(sta) > 1e-6f) ? __frcp_rn(sta) : 0.0f;
        float4 qpa = make_float4(sgna*qp.x, sgna*qp.y, sgna*qp.z, sgna*qp.w);

        float* row = ws + lane * ROWF;
        row[0]=p0x;  row[1]=p0y;  row[2]=p0z;  row[3]=m0x;
        row[4]=m0y;  row[5]=m0z;  row[6]=p1x;  row[7]=p1y;
        row[8]=p1z;  row[9]=m1x;  row[10]=m1y; row[11]=m1z;
        row[12]=qi.x;  row[13]=qi.y;  row[14]=qi.z;  row[15]=qi.w;
        row[16]=qi1a.x; row[17]=qi1a.y; row[18]=qi1a.z; row[19]=qi1a.w;
        row[20]=thm;  row[21]=ism;  row[22]=tha;  row[23]=isa;
        row[24]=qm.x;  row[25]=qm.y;  row[26]=qm.z;  row[27]=qm.w;
        row[28]=qpa.x; row[29]=qpa.y; row[30]=qpa.z; row[31]=qpa.w;
    }
    __syncwarp();

    int r = lane & 7;
    int dq = lane >> 3;
    #pragma unroll
    for (int step = 0; step < 8; ++step) {
        int q = step * 4 + dq;
        int gi = base + q;
        if (gi < nIv) {
            const float* src = ws + q * ROWF + r * 4;
            g_rec[(size_t)gi * 8 + r] = make_float4(src[0], src[1], src[2], src[3]);
        }
    }
}

// ---------------------------------------------------------------------------
// Main kernel: R9 structure (1 query/thread), facos01 blend slerp.
// ---------------------------------------------------------------------------
__global__ __launch_bounds__(TPB)
void camera_spline_kernel(const float* __restrict__ t,
                          const int* __restrict__ Nptr,
                          float* __restrict__ out,
                          int M, int K)
{
    __shared__ float4 s4[WARPS * 256];     // 4KB/warp: 32 records OR outputs
    int lane = threadIdx.x & 31;
    int wid = threadIdx.x >> 5;
    float4* ws4 = s4 + wid * 256;
    float* wsf = (float*)ws4;
    int warpBase = blockIdx.x * TPB + wid * 32;
    int m = warpBase + lane;

    int N = __ldg(Nptr);
    float km1 = (float)(K - 1);
    float nm1 = (float)max(N - 1, 1);
    // Match XLA rounding EXACTLY: t_ctrl = fl( fl(t*(K-1)) * fl(1/(N-1)) )
    float rcp = __fdiv_rn(1.0f, nm1);
    float tv = (m < M) ? t[m] : 0.0f;
    float tc = __fmul_rn(__fmul_rn(tv, km1), rcp);
    int i = min(max((int)floorf(tc), 0), K - 2);
    float u = tc - (float)i;

    // ---- cooperative fetch: 8 LDG.128, each covering 4 whole records ----
    int r = lane & 7;
    int dq = lane >> 3;
    float4 v[8];
    #pragma unroll
    for (int step = 0; step < 8; ++step) {
        int q = step * 4 + dq;
        int idx = __shfl_sync(0xffffffffu, i, q);
        v[step] = g_rec[(size_t)idx * 8 + r];
    }
    #pragma unroll
    for (int step = 0; step < 8; ++step) {
        int q = step * 4 + dq;
        ws4[q * 8 + (r ^ (q & 7))] = v[step];      // XOR swizzle: conflict-free
    }
    __syncwarp();

    // ---- read own record: 8 conflict-free LDS.128 ----
    int q7 = lane & 7;
    float4 P0 = ws4[lane * 8 + (0 ^ q7)];
    float4 P1 = ws4[lane * 8 + (1 ^ q7)];
    float4 P2 = ws4[lane * 8 + (2 ^ q7)];
    float4 P3 = ws4[lane * 8 + (3 ^ q7)];
    float4 P4 = ws4[lane * 8 + (4 ^ q7)];
    float4 P5 = ws4[lane * 8 + (5 ^ q7)];
    float4 P6 = ws4[lane * 8 + (6 ^ q7)];
    float4 P7 = ws4[lane * 8 + (7 ^ q7)];

    // ---- compute ----
    float u2 = u * u;
    float u3 = u2 * u;
    float h00 = 2.0f * u3 - 3.0f * u2 + 1.0f;
    float h10 = u3 - 2.0f * u2 + u;
    float h01 = -2.0f * u3 + 3.0f * u2;
    float h11 = u3 - u2;

    float Tx = h00 * P0.x + h10 * P0.w + h01 * P1.z + h11 * P2.y;
    float Ty = h00 * P0.y + h10 * P1.x + h01 * P1.w + h11 * P2.z;
    float Tz = h00 * P0.z + h10 * P1.y + h01 * P2.x + h11 * P2.w;

    float thm = P5.x, ism = P5.y, tha = P5.z, isa = P5.w;
    float w0m, w1m;
    if (ism != 0.0f) {
        w0m = __sinf((1.0f - u) * thm) * ism;
        w1m = __sinf(u * thm) * ism;
    } else {
        w0m = 1.0f - u;
        w1m = u;
    }
    float4 s_main = make_float4(w0m * P3.x + w1m * P4.x,
                                w0m * P3.y + w1m * P4.y,
                                w0m * P3.z + w1m * P4.z,
                                w0m * P3.w + w1m * P4.w);
    float w0a, w1a;
    if (isa != 0.0f) {
        w0a = __sinf((1.0f - u) * tha) * isa;
        w1a = __sinf(u * tha) * isa;
    } else {
        w0a = 1.0f - u;
        w1a = u;
    }
    float4 s_aux = make_float4(w0a * P6.x + w1a * P7.x,
                               w0a * P6.y + w1a * P7.y,
                               w0a * P6.z + w1a * P7.z,
                               w0a * P6.w + w1a * P7.w);

    // blend slerp: theta via fast poly acos (arg in [0,1] by construction)
    float vbl = 2.0f * u * (1.0f - u);
    float dotb = s_main.x*s_aux.x + s_main.y*s_aux.y + s_main.z*s_aux.z + s_main.w*s_aux.w;
    dotb = fminf(fmaxf(dotb, -1.0f), 1.0f);
    float sgnb = (dotb < 0.0f) ? -1.0f : 1.0f;
    float adb = fminf(fabsf(dotb), 1.0f);
    float thb = facos01(adb);
    float stb = __sinf(thb);
    float w0b, w1b;
    if (fabsf(stb) > 1e-6f) {
        float inv = __frcp_rn(stb);
        w0b = __sinf((1.0f - vbl) * thb) * inv;
        w1b = __sinf(vbl * thb) * inv;
    } else {
        w0b = 1.0f - vbl;
        w1b = vbl;
    }
    w1b *= sgnb;
    float4 q = qnormalize(make_float4(w0b * s_main.x + w1b * s_aux.x,
                                      w0b * s_main.y + w1b * s_aux.y,
                                      w0b * s_main.z + w1b * s_aux.z,
                                      w0b * s_main.w + w1b * s_aux.w));

    float w = q.x, x = q.y, y = q.z, z = q.w;
    float xx = x * x, yy = y * y, zz = z * z;
    float xy = x * y, xz = x * z, yz = y * z;
    float wx = w * x, wy = w * y, wz = w * z;

    __syncwarp();   // all record reads done before staging overwrites them

    // ---- scatter outputs: R at q*9+c (9 coprime 32), T at 288+q*3+c ----
    if (m < M) {
        float* rr = wsf + lane * 9;
        rr[0] = 1.0f - 2.0f * (yy + zz);
        rr[1] = 2.0f * (xy - wz);
        rr[2] = 2.0f * (xz + wy);
        rr[3] = 2.0f * (xy + wz);
        rr[4] = 1.0f - 2.0f * (xx + zz);
        rr[5] = 2.0f * (yz - wx);
        rr[6] = 2.0f * (xz - wy);
        rr[7] = 2.0f * (yz + wx);
        rr[8] = 1.0f - 2.0f * (xx + yy);
        float* tt = wsf + 288 + lane * 3;
        tt[0] = Tx; tt[1] = Ty; tt[2] = Tz;
    }
    __syncwarp();

    // ---- warp-local coalesced writeback (evict-first stores) ----
    int count = min(32, M - warpBase);
    if (count <= 0) return;

    if (count == 32) {
        float4* dstR = (float4*)(out + (size_t)warpBase * 9);   // warpBase%32==0 -> aligned
        const float4* srcR = (const float4*)wsf;
        #pragma unroll
        for (int n = lane; n < 72; n += 32)
            __stcs(dstR + n, srcR[n]);
        size_t tBase = (size_t)M * 9 + (size_t)warpBase * 3;
        if ((tBase & 3) == 0) {
            float4* dstT = (float4*)(out + tBase);
            const float4* srcT = (const float4*)(wsf + 288);
            if (lane < 24)
                __stcs(dstT + lane, srcT[lane]);
        } else {
            float* dstT = out + tBase;
            for (int e = lane; e < 96; e += 32)
                dstT[e] = wsf[288 + e];
        }
    } else {
        float* dstR = out + (size_t)warpBase * 9;
        for (int e = lane; e < count * 9; e += 32)
            dstR[e] = wsf[e];
        float* dstT = out + (size_t)M * 9 + (size_t)warpBase * 3;
        for (int e = lane; e < count * 3; e += 32)
            dstT[e] = wsf[288 + e];
    }
}

// ---------------------------------------------------------------------------
// Fallback for K-1 > CAPI: direct gather.
// ---------------------------------------------------------------------------
__global__ __launch_bounds__(256)
void camera_spline_kernel_direct(const float* __restrict__ t,
                                 const float* __restrict__ ctrl_trans,
                                 const float* __restrict__ ctrl_quats,
                                 const int* __restrict__ Nptr,
                                 float* __restrict__ out,
                                 int M, int K)
{
    int m = blockIdx.x * blockDim.x + threadIdx.x;
    if (m >= M) return;

    int N = __ldg(Nptr);
    float km1 = (float)(K - 1);
    float nm1 = (float)max(N - 1, 1);
    float rcp = __fdiv_rn(1.0f, nm1);
    float tc = __fmul_rn(__fmul_rn(t[m], km1), rcp);
    int i = min(max((int)floorf(tc), 0), K - 2);
    float u = tc - (float)i;
    int im1 = max(i - 1, 0);
    int ip2 = min(i + 2, K - 1);

    float3 p0 = make_float3(ctrl_trans[3*i+0], ctrl_trans[3*i+1], ctrl_trans[3*i+2]);
    float3 p1 = make_float3(ctrl_trans[3*(i+1)+0], ctrl_trans[3*(i+1)+1], ctrl_trans[3*(i+1)+2]);
    float3 pm = make_float3(ctrl_trans[3*im1+0], ctrl_trans[3*im1+1], ctrl_trans[3*im1+2]);
    float3 pp = make_float3(ctrl_trans[3*ip2+0], ctrl_trans[3*ip2+1], ctrl_trans[3*ip2+2]);

    float3 d01 = make_float3(p1.x - p0.x, p1.y - p0.y, p1.z - p0.z);
    float3 m0 = (i > 0) ? make_float3(0.5f*(p1.x-pm.x), 0.5f*(p1.y-pm.y), 0.5f*(p1.z-pm.z)) : d01;
    float3 m1 = (i + 1 < K - 1) ? make_float3(0.5f*(pp.x-p0.x), 0.5f*(pp.y-p0.y), 0.5f*(pp.z-p0.z)) : d01;

    float u2 = u * u, u3 = u2 * u;
    float h00 = 2.0f*u3 - 3.0f*u2 + 1.0f;
    float h10 = u3 - 2.0f*u2 + u;
    float h01 = -2.0f*u3 + 3.0f*u2;
    float h11 = u3 - u2;
    float Tx = h00*p0.x + h10*m0.x + h01*p1.x + h11*m1.x;
    float Ty = h00*p0.y + h10*m0.y + h01*p1.y + h11*m1.y;
    float Tz = h00*p0.z + h10*m0.z + h01*p1.z + h11*m1.z;

    const float4* quats = (const float4*)ctrl_quats;
    float4 q_i  = qnormalize(quats[i]);
    float4 q_i1 = qnormalize(quats[i + 1]);
    float4 q_m  = qnormalize(quats[im1]);
    float4 q_p  = qnormalize(quats[ip2]);
    float4 s_main = qslerp(q_i, q_i1, u);
    float4 s_aux  = qslerp(q_m, q_p, u);
    float4 q = qnormalize(qslerp(s_main, s_aux, 2.0f * u * (1.0f - u)));

    float w = q.x, x = q.y, y = q.z, z = q.w;
    float* R = out + (size_t)m * 9;
    R[0] = 1.0f - 2.0f * (y*y + z*z);
    R[1] = 2.0f * (x*y - w*z);
    R[2] = 2.0f * (x*z + w*y);
    R[3] = 2.0f * (x*y + w*z);
    R[4] = 1.0f - 2.0f * (x*x + z*z);
    R[5] = 2.0f * (y*z - w*x);
    R[6] = 2.0f * (x*z - w*y);
    R[7] = 2.0f * (y*z + w*x);
    R[8] = 1.0f - 2.0f * (x*x + y*y);
    float* Tout = out + (size_t)M * 9 + (size_t)m * 3;
    Tout[0] = Tx; Tout[1] = Ty; Tout[2] = Tz;
}

extern "C" void kernel_launch(void* const* d_in, const int* in_sizes, int n_in,
                              void* d_out, int out_size)
{
    const float* t          = (const float*)d_in[0];
    const float* ctrl_trans = (const float*)d_in[1];
    const float* ctrl_quats = (const float*)d_in[2];
    const int*   Nptr       = (const int*)d_in[3];

    int M = in_sizes[0];
    int K = in_sizes[1] / 3;

    float* out = (float*)d_out;

    if (K - 1 <= CAPI) {
        int nIv = K - 1;
        int pblocks = (nIv + TPB - 1) / TPB;
        precompute_intervals<<<pblocks, TPB>>>(ctrl_trans, ctrl_quats, K);
        int blocks = (M + TPB - 1) / TPB;
        camera_spline_kernel<<<blocks, TPB>>>(t, Nptr, out, M, K);
    } else {
        int blocks = (M + 255) / 256;
        camera_spline_kernel_direct<<<blocks, 256>>>(t, ctrl_trans, ctrl_quats, Nptr, out, M, K);
    }
}

// round 15
// speedup vs baseline: 1.4749x; 1.2581x over previous
#include <cuda_runtime.h>
#include <cuda_bf16.h>
#include <cstdint>

// CameraSpline pose evaluation.
// Inputs (metadata order): t [M] f32, ctrl_trans [K,3] f32, ctrl_quats [K,4] f32, N [1] i32.
// Output: R [M,3,3] flattened (9*M floats) followed by T [M,3] (3*M floats).
//
// R14 -> R15: record fetch switched from LDG->reg->STS (64 L1 wavefronts per
// warp) to cp.async.cg global->smem (LDGSTS, no register roundtrip, L1-bypass)
// inside the proven R9 one-shot shape. R11 already evidenced cp.async slashes
// L1 pressure; its regression was the persistent-loop structure, now dropped.

#define TPB 128
#define WARPS (TPB / 32)
#define CAPI 524288                // max intervals in the record table

#define CP_ASYNC16(dst32, src)                                              \
    asm volatile("cp.async.cg.shared.global [%0], [%1], 16;"                \
                 :: "r"(dst32), "l"(src) : "memory")
#define CP_ASYNC_COMMIT() asm volatile("cp.async.commit_group;" ::: "memory")
#define CP_ASYNC_WAIT0()  asm volatile("cp.async.wait_group 0;" ::: "memory")

// One 128B record (8 float4 parts) per interval i:
//  p0: p0x p0y p0z m0x | p1: m0y m0z p1x p1y | p2: p1z m1x m1y m1z
//  p3: q_i | p4: q_i1_adj (sign folded) | p5: thm ism tha isa
//  p6: q_im1 | p7: q_ip2_adj (sign folded)
__device__ __align__(128) float4 g_rec[(size_t)CAPI * 8];

__device__ __forceinline__ float4 qnormalize(float4 q) {
    float inv = rsqrtf(q.x * q.x + q.y * q.y + q.z * q.z + q.w * q.w);
    return make_float4(q.x * inv, q.y * inv, q.z * inv, q.w * inv);
}

// acos(x) for x in [0,1]: sqrt(1-x) * poly7 (Hastings; |err| ~ 2e-8).
__device__ __forceinline__ float facos01(float x) {
    float p = fmaf(x, -0.0012624911f, 0.0066700901f);
    p = fmaf(x, p, -0.0170881256f);
    p = fmaf(x, p, 0.0308918810f);
    p = fmaf(x, p, -0.0501743046f);
    p = fmaf(x, p, 0.0889789874f);
    p = fmaf(x, p, -0.2145988016f);
    p = fmaf(x, p, 1.5707963050f);
    return sqrtf(fmaxf(1.0f - x, 0.0f)) * p;
}

// Full slerp (direct fallback path only).
__device__ __forceinline__ float4 qslerp(float4 q0, float4 q1, float u) {
    float dot = q0.x * q1.x + q0.y * q1.y + q0.z * q1.z + q0.w * q1.w;
    dot = fminf(fmaxf(dot, -1.0f), 1.0f);
    float sgn = (dot < 0.0f) ? -1.0f : 1.0f;
    float ad = fminf(fabsf(dot), 1.0f);
    float theta = acosf(ad);
    float st = __sinf(theta);
    float w0, w1;
    if (fabsf(st) > 1e-6f) {
        float inv = __frcp_rn(st);
        w0 = __sinf((1.0f - u) * theta) * inv;
        w1 = __sinf(u * theta) * inv;
    } else {
        w0 = 1.0f - u;
        w1 = u;
    }
    w1 *= sgn;
    return make_float4(w0 * q0.x + w1 * q1.x,
                       w0 * q0.y + w1 * q1.y,
                       w0 * q0.z + w1 * q1.z,
                       w0 * q0.w + w1 * q1.w);
}

// ---------------------------------------------------------------------------
// Precompute: one 128B record per interval, written coalesced via smem.
// ---------------------------------------------------------------------------
#define ROWF 33
__global__ __launch_bounds__(TPB)
void precompute_intervals(const float* __restrict__ trans,
                          const float* __restrict__ quats,
                          int K)
{
    __shared__ float s[WARPS * 32 * ROWF];
    int lane = threadIdx.x & 31;
    int wid = threadIdx.x >> 5;
    float* ws = s + wid * 32 * ROWF;
    int nIv = K - 1;
    int base = (blockIdx.x * WARPS + wid) * 32;
    if (base >= nIv) return;

    int i = min(base + lane, nIv - 1);     // clamp; extra rows never stored
    {
        int im1 = max(i - 1, 0);
        int ip2 = min(i + 2, K - 1);
        float p0x = trans[3*i+0], p0y = trans[3*i+1], p0z = trans[3*i+2];
        float p1x = trans[3*(i+1)+0], p1y = trans[3*(i+1)+1], p1z = trans[3*(i+1)+2];
        float pmx = trans[3*im1+0], pmy = trans[3*im1+1], pmz = trans[3*im1+2];
        float ppx = trans[3*ip2+0], ppy = trans[3*ip2+1], ppz = trans[3*ip2+2];

        float d01x = p1x - p0x, d01y = p1y - p0y, d01z = p1z - p0z;
        float m0x, m0y, m0z, m1x, m1y, m1z;
        if (i > 0) { m0x = 0.5f*(p1x - pmx); m0y = 0.5f*(p1y - pmy); m0z = 0.5f*(p1z - pmz); }
        else       { m0x = d01x; m0y = d01y; m0z = d01z; }
        if (i + 1 < K - 1) { m1x = 0.5f*(ppx - p0x); m1y = 0.5f*(ppy - p0y); m1z = 0.5f*(ppz - p0z); }
        else               { m1x = d01x; m1y = d01y; m1z = d01z; }

        const float4* q4 = (const float4*)quats;
        float4 qi  = qnormalize(q4[i]);
        float4 qi1 = qnormalize(q4[i + 1]);
        float4 qm  = qnormalize(q4[im1]);
        float4 qp  = qnormalize(q4[ip2]);

        float dm = qi.x*qi1.x + qi.y*qi1.y + qi.z*qi1.z + qi.w*qi1.w;
        dm = fminf(fmaxf(dm, -1.0f), 1.0f);
        float sgnm = (dm < 0.0f) ? -1.0f : 1.0f;
        float thm = acosf(fminf(fabsf(dm), 1.0f));
        float stm = __sinf(thm);
        float ism = (fabsf(stm) > 1e-6f) ? __frcp_rn(stm) : 0.0f;
        float4 qi1a = make_float4(sgnm*qi1.x, sgnm*qi1.y, sgnm*qi1.z, sgnm*qi1.w);

        float da = qm.x*qp.x + qm.y*qp.y + qm.z*qp.z + qm.w*qp.w;
        da = fminf(fmaxf(da, -1.0f), 1.0f);
        float sgna = (da < 0.0f) ? -1.0f : 1.0f;
        float tha = acosf(fminf(fabsf(da), 1.0f));
        float sta = __sinf(tha);
        float isa = (fabsf(sta) > 1e-6f) ? __frcp_rn(sta) : 0.0f;
        float4 qpa = make_float4(sgna*qp.x, sgna*qp.y, sgna*qp.z, sgna*qp.w);

        float* row = ws + lane * ROWF;
        row[0]=p0x;  row[1]=p0y;  row[2]=p0z;  row[3]=m0x;
        row[4]=m0y;  row[5]=m0z;  row[6]=p1x;  row[7]=p1y;
        row[8]=p1z;  row[9]=m1x;  row[10]=m1y; row[11]=m1z;
        row[12]=qi.x;  row[13]=qi.y;  row[14]=qi.z;  row[15]=qi.w;
        row[16]=qi1a.x; row[17]=qi1a.y; row[18]=qi1a.z; row[19]=qi1a.w;
        row[20]=thm;  row[21]=ism;  row[22]=tha;  row[23]=isa;
        row[24]=qm.x;  row[25]=qm.y;  row[26]=qm.z;  row[27]=qm.w;
        row[28]=qpa.x; row[29]=qpa.y; row[30]=qpa.z; row[31]=qpa.w;
    }
    __syncwarp();

    int r = lane & 7;
    int dq = lane >> 3;
    #pragma unroll
    for (int step = 0; step < 8; ++step) {
        int q = step * 4 + dq;
        int gi = base + q;
        if (gi < nIv) {
            const float* src = ws + q * ROWF + r * 4;
            g_rec[(size_t)gi * 8 + r] = make_float4(src[0], src[1], src[2], src[3]);
        }
    }
}

// ---------------------------------------------------------------------------
// Main kernel: R9 structure, record fetch via cp.async.cg (global -> smem).
// ---------------------------------------------------------------------------
__global__ __launch_bounds__(TPB)
void camera_spline_kernel(const float* __restrict__ t,
                          const int* __restrict__ Nptr,
                          float* __restrict__ out,
                          int M, int K)
{
    __shared__ float4 s4[WARPS * 256];     // 4KB/warp: 32 records OR outputs
    int lane = threadIdx.x & 31;
    int wid = threadIdx.x >> 5;
    float4* ws4 = s4 + wid * 256;
    float* wsf = (float*)ws4;
    int warpBase = blockIdx.x * TPB + wid * 32;
    int m = warpBase + lane;

    int N = __ldg(Nptr);
    float km1 = (float)(K - 1);
    float nm1 = (float)max(N - 1, 1);
    // Match XLA rounding EXACTLY: t_ctrl = fl( fl(t*(K-1)) * fl(1/(N-1)) )
    float rcp = __fdiv_rn(1.0f, nm1);
    float tv = (m < M) ? t[m] : 0.0f;
    float tc = __fmul_rn(__fmul_rn(tv, km1), rcp);
    int i = min(max((int)floorf(tc), 0), K - 2);
    float u = tc - (float)i;

    // ---- cooperative fetch via cp.async.cg: 8 x 16B per lane,
    //      each group of 4 lanes covers one whole 128B record ----
    int r = lane & 7;
    int dq = lane >> 3;
    #pragma unroll
    for (int step = 0; step < 8; ++step) {
        int q = step * 4 + dq;
        int idx = __shfl_sync(0xffffffffu, i, q);
        const float4* src = &g_rec[(size_t)idx * 8 + r];
        uint32_t dst = (uint32_t)__cvta_generic_to_shared(
            &ws4[q * 8 + (r ^ (q & 7))]);          // XOR swizzle: conflict-free
        CP_ASYNC16(dst, src);
    }
    CP_ASYNC_COMMIT();
    CP_ASYNC_WAIT0();
    __syncwarp();

    // ---- read own record: 8 conflict-free LDS.128 ----
    int q7 = lane & 7;
    float4 P0 = ws4[lane * 8 + (0 ^ q7)];
    float4 P1 = ws4[lane * 8 + (1 ^ q7)];
    float4 P2 = ws4[lane * 8 + (2 ^ q7)];
    float4 P3 = ws4[lane * 8 + (3 ^ q7)];
    float4 P4 = ws4[lane * 8 + (4 ^ q7)];
    float4 P5 = ws4[lane * 8 + (5 ^ q7)];
    float4 P6 = ws4[lane * 8 + (6 ^ q7)];
    float4 P7 = ws4[lane * 8 + (7 ^ q7)];

    // ---- compute ----
    float u2 = u * u;
    float u3 = u2 * u;
    float h00 = 2.0f * u3 - 3.0f * u2 + 1.0f;
    float h10 = u3 - 2.0f * u2 + u;
    float h01 = -2.0f * u3 + 3.0f * u2;
    float h11 = u3 - u2;

    float Tx = h00 * P0.x + h10 * P0.w + h01 * P1.z + h11 * P2.y;
    float Ty = h00 * P0.y + h10 * P1.x + h01 * P1.w + h11 * P2.z;
    float Tz = h00 * P0.z + h10 * P1.y + h01 * P2.x + h11 * P2.w;

    float thm = P5.x, ism = P5.y, tha = P5.z, isa = P5.w;
    float w0m, w1m;
    if (ism != 0.0f) {
        w0m = __sinf((1.0f - u) * thm) * ism;
        w1m = __sinf(u * thm) * ism;
    } else {
        w0m = 1.0f - u;
        w1m = u;
    }
    float4 s_main = make_float4(w0m * P3.x + w1m * P4.x,
                                w0m * P3.y + w1m * P4.y,
                                w0m * P3.z + w1m * P4.z,
                                w0m * P3.w + w1m * P4.w);
    float w0a, w1a;
    if (isa != 0.0f) {
        w0a = __sinf((1.0f - u) * tha) * isa;
        w1a = __sinf(u * tha) * isa;
    } else {
        w0a = 1.0f - u;
        w1a = u;
    }
    float4 s_aux = make_float4(w0a * P6.x + w1a * P7.x,
                               w0a * P6.y + w1a * P7.y,
                               w0a * P6.z + w1a * P7.z,
                               w0a * P6.w + w1a * P7.w);

    // blend slerp: theta via fast poly acos (arg in [0,1] by construction)
    float vbl = 2.0f * u * (1.0f - u);
    float dotb = s_main.x*s_aux.x + s_main.y*s_aux.y + s_main.z*s_aux.z + s_main.w*s_aux.w;
    dotb = fminf(fmaxf(dotb, -1.0f), 1.0f);
    float sgnb = (dotb < 0.0f) ? -1.0f : 1.0f;
    float adb = fminf(fabsf(dotb), 1.0f);
    float thb = facos01(adb);
    float stb = __sinf(thb);
    float w0b, w1b;
    if (fabsf(stb) > 1e-6f) {
        float inv = __frcp_rn(stb);
        w0b = __sinf((1.0f - vbl) * thb) * inv;
        w1b = __sinf(vbl * thb) * inv;
    } else {
        w0b = 1.0f - vbl;
        w1b = vbl;
    }
    w1b *= sgnb;
    float4 q = qnormalize(make_float4(w0b * s_main.x + w1b * s_aux.x,
                                      w0b * s_main.y + w1b * s_aux.y,
                                      w0b * s_main.z + w1b * s_aux.z,
                                      w0b * s_main.w + w1b * s_aux.w));

    float w = q.x, x = q.y, y = q.z, z = q.w;
    float xx = x * x, yy = y * y, zz = z * z;
    float xy = x * y, xz = x * z, yz = y * z;
    float wx = w * x, wy = w * y, wz = w * z;

    __syncwarp();   // all record reads done before staging overwrites them

    // ---- scatter outputs: R at q*9+c (9 coprime 32), T at 288+q*3+c ----
    if (m < M) {
        float* rr = wsf + lane * 9;
        rr[0] = 1.0f - 2.0f * (yy + zz);
        rr[1] = 2.0f * (xy - wz);
        rr[2] = 2.0f * (xz + wy);
        rr[3] = 2.0f * (xy + wz);
        rr[4] = 1.0f - 2.0f * (xx + zz);
        rr[5] = 2.0f * (yz - wx);
        rr[6] = 2.0f * (xz - wy);
        rr[7] = 2.0f * (yz + wx);
        rr[8] = 1.0f - 2.0f * (xx + yy);
        float* tt = wsf + 288 + lane * 3;
        tt[0] = Tx; tt[1] = Ty; tt[2] = Tz;
    }
    __syncwarp();

    // ---- warp-local coalesced writeback (evict-first stores) ----
    int count = min(32, M - warpBase);
    if (count <= 0) return;

    if (count == 32) {
        float4* dstR = (float4*)(out + (size_t)warpBase * 9);   // warpBase%32==0 -> aligned
        const float4* srcR = (const float4*)wsf;
        #pragma unroll
        for (int n = lane; n < 72; n += 32)
            __stcs(dstR + n, srcR[n]);
        size_t tBase = (size_t)M * 9 + (size_t)warpBase * 3;
        if ((tBase & 3) == 0) {
            float4* dstT = (float4*)(out + tBase);
            const float4* srcT = (const float4*)(wsf + 288);
            if (lane < 24)
                __stcs(dstT + lane, srcT[lane]);
        } else {
            float* dstT = out + tBase;
            for (int e = lane; e < 96; e += 32)
                dstT[e] = wsf[288 + e];
        }
    } else {
        float* dstR = out + (size_t)warpBase * 9;
        for (int e = lane; e < count * 9; e += 32)
            dstR[e] = wsf[e];
        float* dstT = out + (size_t)M * 9 + (size_t)warpBase * 3;
        for (int e = lane; e < count * 3; e += 32)
            dstT[e] = wsf[288 + e];
    }
}

// ---------------------------------------------------------------------------
// Fallback for K-1 > CAPI: direct gather.
// ---------------------------------------------------------------------------
__global__ __launch_bounds__(256)
void camera_spline_kernel_direct(const float* __restrict__ t,
                                 const float* __restrict__ ctrl_trans,
                                 const float* __restrict__ ctrl_quats,
                                 const int* __restrict__ Nptr,
                                 float* __restrict__ out,
                                 int M, int K)
{
    int m = blockIdx.x * blockDim.x + threadIdx.x;
    if (m >= M) return;

    int N = __ldg(Nptr);
    float km1 = (float)(K - 1);
    float nm1 = (float)max(N - 1, 1);
    float rcp = __fdiv_rn(1.0f, nm1);
    float tc = __fmul_rn(__fmul_rn(t[m], km1), rcp);
    int i = min(max((int)floorf(tc), 0), K - 2);
    float u = tc - (float)i;
    int im1 = max(i - 1, 0);
    int ip2 = min(i + 2, K - 1);

    float3 p0 = make_float3(ctrl_trans[3*i+0], ctrl_trans[3*i+1], ctrl_trans[3*i+2]);
    float3 p1 = make_float3(ctrl_trans[3*(i+1)+0], ctrl_trans[3*(i+1)+1], ctrl_trans[3*(i+1)+2]);
    float3 pm = make_float3(ctrl_trans[3*im1+0], ctrl_trans[3*im1+1], ctrl_trans[3*im1+2]);
    float3 pp = make_float3(ctrl_trans[3*ip2+0], ctrl_trans[3*ip2+1], ctrl_trans[3*ip2+2]);

    float3 d01 = make_float3(p1.x - p0.x, p1.y - p0.y, p1.z - p0.z);
    float3 m0 = (i > 0) ? make_float3(0.5f*(p1.x-pm.x), 0.5f*(p1.y-pm.y), 0.5f*(p1.z-pm.z)) : d01;
    float3 m1 = (i + 1 < K - 1) ? make_float3(0.5f*(pp.x-p0.x), 0.5f*(pp.y-p0.y), 0.5f*(pp.z-p0.z)) : d01;

    float u2 = u * u, u3 = u2 * u;
    float h00 = 2.0f*u3 - 3.0f*u2 + 1.0f;
    float h10 = u3 - 2.0f*u2 + u;
    float h01 = -2.0f*u3 + 3.0f*u2;
    float h11 = u3 - u2;
    float Tx = h00*p0.x + h10*m0.x + h01*p1.x + h11*m1.x;
    float Ty = h00*p0.y + h10*m0.y + h01*p1.y + h11*m1.y;
    float Tz = h00*p0.z + h10*m0.z + h01*p1.z + h11*m1.z;

    const float4* quats = (const float4*)ctrl_quats;
    float4 q_i  = qnormalize(quats[i]);
    float4 q_i1 = qnormalize(quats[i + 1]);
    float4 q_m  = qnormalize(quats[im1]);
    float4 q_p  = qnormalize(quats[ip2]);
    float4 s_main = qslerp(q_i, q_i1, u);
    float4 s_aux  = qslerp(q_m, q_p, u);
    float4 q = qnormalize(qslerp(s_main, s_aux, 2.0f * u * (1.0f - u)));

    float w = q.x, x = q.y, y = q.z, z = q.w;
    float* R = out + (size_t)m * 9;
    R[0] = 1.0f - 2.0f * (y*y + z*z);
    R[1] = 2.0f * (x*y - w*z);
    R[2] = 2.0f * (x*z + w*y);
    R[3] = 2.0f * (x*y + w*z);
    R[4] = 1.0f - 2.0f * (x*x + z*z);
    R[5] = 2.0f * (y*z - w*x);
    R[6] = 2.0f * (x*z - w*y);
    R[7] = 2.0f * (y*z + w*x);
    R[8] = 1.0f - 2.0f * (x*x + y*y);
    float* Tout = out + (size_t)M * 9 + (size_t)m * 3;
    Tout[0] = Tx; Tout[1] = Ty; Tout[2] = Tz;
}

extern "C" void kernel_launch(void* const* d_in, const int* in_sizes, int n_in,
                              void* d_out, int out_size)
{
    const float* t          = (const float*)d_in[0];
    const float* ctrl_trans = (const float*)d_in[1];
    const float* ctrl_quats = (const float*)d_in[2];
    const int*   Nptr       = (const int*)d_in[3];

    int M = in_sizes[0];
    int K = in_sizes[1] / 3;

    float* out = (float*)d_out;

    if (K - 1 <= CAPI) {
        int nIv = K - 1;
        int pblocks = (nIv + TPB - 1) / TPB;
        precompute_intervals<<<pblocks, TPB>>>(ctrl_trans, ctrl_quats, K);
        int blocks = (M + TPB - 1) / TPB;
        camera_spline_kernel<<<blocks, TPB>>>(t, Nptr, out, M, K);
    } else {
        int blocks = (M + 255) / 256;
        camera_spline_kernel_direct<<<blocks, 256>>>(t, ctrl_trans, ctrl_quats, Nptr, out, M, K);
    }
}

// round 17
// speedup vs baseline: 1.4779x; 1.0020x over previous
#include <cuda_runtime.h>
#include <cuda_bf16.h>
#include <cstdint>

// CameraSpline pose evaluation.
// Inputs (metadata order): t [M] f32, ctrl_trans [K,3] f32, ctrl_quats [K,4] f32, N [1] i32.
// Output: R [M,3,3] flattened (9*M floats) followed by T [M,3] (3*M floats).
//
// R15 -> R16 (resubmitted R17; R16 bench was an infra failure).
// Kernel is issue-bound at 69.9%:
//  * uniform __fdiv_rn(1/(N-1)) (a ~20-inst subroutine PER THREAD) moved to
//    the precompute kernel; main loads a precomputed {km1, rcp} float2.
//  * final quat normalization folded into the R scale (s = 2*rcp(|q|^2),
//    products from raw quat) — drops rsqrt + 4 normalize muls.
//  * memory plan unchanged from R15 (cp.async.cg gather, smem-staged output).

#define TPB 128
#define WARPS (TPB / 32)
#define CAPI 524288                // max intervals in the record table

#define CP_ASYNC16(dst32, src)                                              \
    asm volatile("cp.async.cg.shared.global [%0], [%1], 16;"                \
                 :: "r"(dst32), "l"(src) : "memory")
#define CP_ASYNC_COMMIT() asm volatile("cp.async.commit_group;" ::: "memory")
#define CP_ASYNC_WAIT0()  asm volatile("cp.async.wait_group 0;" ::: "memory")

// One 128B record (8 float4 parts) per interval i:
//  p0: p0x p0y p0z m0x | p1: m0y m0z p1x p1y | p2: p1z m1x m1y m1z
//  p3: q_i | p4: q_i1_adj (sign folded) | p5: thm ism tha isa
//  p6: q_im1 | p7: q_ip2_adj (sign folded)
__device__ __align__(128) float4 g_rec[(size_t)CAPI * 8];
__device__ float2 g_consts;        // {km1, rcp(nm1)} computed once on device

__device__ __forceinline__ float4 qnormalize(float4 q) {
    float inv = rsqrtf(q.x * q.x + q.y * q.y + q.z * q.z + q.w * q.w);
    return make_float4(q.x * inv, q.y * inv, q.z * inv, q.w * inv);
}

// acos(x) for x in [0,1]: sqrt(1-x) * poly7 (Hastings; |err| ~ 2e-8).
__device__ __forceinline__ float facos01(float x) {
    float p = fmaf(x, -0.0012624911f, 0.0066700901f);
    p = fmaf(x, p, -0.0170881256f);
    p = fmaf(x, p, 0.0308918810f);
    p = fmaf(x, p, -0.0501743046f);
    p = fmaf(x, p, 0.0889789874f);
    p = fmaf(x, p, -0.2145988016f);
    p = fmaf(x, p, 1.5707963050f);
    return sqrtf(fmaxf(1.0f - x, 0.0f)) * p;
}

// Full slerp (direct fallback path only).
__device__ __forceinline__ float4 qslerp(float4 q0, float4 q1, float u) {
    float dot = q0.x * q1.x + q0.y * q1.y + q0.z * q1.z + q0.w * q1.w;
    dot = fminf(fmaxf(dot, -1.0f), 1.0f);
    float sgn = (dot < 0.0f) ? -1.0f : 1.0f;
    float ad = fminf(fabsf(dot), 1.0f);
    float theta = acosf(ad);
    float st = __sinf(theta);
    float w0, w1;
    if (fabsf(st) > 1e-6f) {
        float inv = __frcp_rn(st);
        w0 = __sinf((1.0f - u) * theta) * inv;
        w1 = __sinf(u * theta) * inv;
    } else {
        w0 = 1.0f - u;
        w1 = u;
    }
    w1 *= sgn;
    return make_float4(w0 * q0.x + w1 * q1.x,
                       w0 * q0.y + w1 * q1.y,
                       w0 * q0.z + w1 * q1.z,
                       w0 * q0.w + w1 * q1.w);
}

// ---------------------------------------------------------------------------
// Precompute: one 128B record per interval, written coalesced via smem.
// Also computes the uniform {km1, rcp} pair once.
// ---------------------------------------------------------------------------
#define ROWF 33
__global__ __launch_bounds__(TPB)
void precompute_intervals(const float* __restrict__ trans,
                          const float* __restrict__ quats,
                          const int* __restrict__ Nptr,
                          int K)
{
    if (blockIdx.x == 0 && threadIdx.x == 0) {
        int N = *Nptr;
        float km1 = (float)(K - 1);
        float nm1 = (float)max(N - 1, 1);
        // Match XLA rounding: reference does t*(K-1) then * fl(1/(N-1)).
        g_consts = make_float2(km1, __fdiv_rn(1.0f, nm1));
    }

    __shared__ float s[WARPS * 32 * ROWF];
    int lane = threadIdx.x & 31;
    int wid = threadIdx.x >> 5;
    float* ws = s + wid * 32 * ROWF;
    int nIv = K - 1;
    int base = (blockIdx.x * WARPS + wid) * 32;
    if (base >= nIv) return;

    int i = min(base + lane, nIv - 1);     // clamp; extra rows never stored
    {
        int im1 = max(i - 1, 0);
        int ip2 = min(i + 2, K - 1);
        float p0x = trans[3*i+0], p0y = trans[3*i+1], p0z = trans[3*i+2];
        float p1x = trans[3*(i+1)+0], p1y = trans[3*(i+1)+1], p1z = trans[3*(i+1)+2];
        float pmx = trans[3*im1+0], pmy = trans[3*im1+1], pmz = trans[3*im1+2];
        float ppx = trans[3*ip2+0], ppy = trans[3*ip2+1], ppz = trans[3*ip2+2];

        float d01x = p1x - p0x, d01y = p1y - p0y, d01z = p1z - p0z;
        float m0x, m0y, m0z, m1x, m1y, m1z;
        if (i > 0) { m0x = 0.5f*(p1x - pmx); m0y = 0.5f*(p1y - pmy); m0z = 0.5f*(p1z - pmz); }
        else       { m0x = d01x; m0y = d01y; m0z = d01z; }
        if (i + 1 < K - 1) { m1x = 0.5f*(ppx - p0x); m1y = 0.5f*(ppy - p0y); m1z = 0.5f*(ppz - p0z); }
        else               { m1x = d01x; m1y = d01y; m1z = d01z; }

        const float4* q4 = (const float4*)quats;
        float4 qi  = qnormalize(q4[i]);
        float4 qi1 = qnormalize(q4[i + 1]);
        float4 qm  = qnormalize(q4[im1]);
        float4 qp  = qnormalize(q4[ip2]);

        float dm = qi.x*qi1.x + qi.y*qi1.y + qi.z*qi1.z + qi.w*qi1.w;
        dm = fminf(fmaxf(dm, -1.0f), 1.0f);
        float sgnm = (dm < 0.0f) ? -1.0f : 1.0f;
        float thm = acosf(fminf(fabsf(dm), 1.0f));
        float stm = __sinf(thm);
        float ism = (fabsf(stm) > 1e-6f) ? __frcp_rn(stm) : 0.0f;
        float4 qi1a = make_float4(sgnm*qi1.x, sgnm*qi1.y, sgnm*qi1.z, sgnm*qi1.w);

        float da = qm.x*qp.x + qm.y*qp.y + qm.z*qp.z + qm.w*qp.w;
        da = fminf(fmaxf(da, -1.0f), 1.0f);
        float sgna = (da < 0.0f) ? -1.0f : 1.0f;
        float tha = acosf(fminf(fabsf(da), 1.0f));
        float sta = __sinf(tha);
        float isa = (fabsf(sta) > 1e-6f) ? __frcp_rn(sta) : 0.0f;
        float4 qpa = make_float4(sgna*qp.x, sgna*qp.y, sgna*qp.z, sgna*qp.w);

        float* row = ws + lane * ROWF;
        row[0]=p0x;  row[1]=p0y;  row[2]=p0z;  row[3]=m0x;
        row[4]=m0y;  row[5]=m0z;  row[6]=p1x;  row[7]=p1y;
        row[8]=p1z;  row[9]=m1x;  row[10]=m1y; row[11]=m1z;
        row[12]=qi.x;  row[13]=qi.y;  row[14]=qi.z;  row[15]=qi.w;
        row[16]=qi1a.x; row[17]=qi1a.y; row[18]=qi1a.z; row[19]=qi1a.w;
        row[20]=thm;  row[21]=ism;  row[22]=tha;  row[23]=isa;
        row[24]=qm.x;  row[25]=qm.y;  row[26]=qm.z;  row[27]=qm.w;
        row[28]=qpa.x; row[29]=qpa.y; row[30]=qpa.z; row[31]=qpa.w;
    }
    __syncwarp();

    int r = lane & 7;
    int dq = lane >> 3;
    #pragma unroll
    for (int step = 0; step < 8; ++step) {
        int q = step * 4 + dq;
        int gi = base + q;
        if (gi < nIv) {
            const float* src = ws + q * ROWF + r * 4;
            g_rec[(size_t)gi * 8 + r] = make_float4(src[0], src[1], src[2], src[3]);
        }
    }
}

// ---------------------------------------------------------------------------
// Main kernel: R15 structure, uniform consts preloaded, normalization folded.
// ---------------------------------------------------------------------------
__global__ __launch_bounds__(TPB)
void camera_spline_kernel(const float* __restrict__ t,
                          float* __restrict__ out,
                          int M, int K)
{
    __shared__ float4 s4[WARPS * 256];     // 4KB/warp: 32 records OR outputs
    int lane = threadIdx.x & 31;
    int wid = threadIdx.x >> 5;
    float4* ws4 = s4 + wid * 256;
    float* wsf = (float*)ws4;
    int warpBase = blockIdx.x * TPB + wid * 32;
    int m = warpBase + lane;

    float2 cs = __ldg(&g_consts);
    float km1 = cs.x;
    float rcp = cs.y;
    // Match XLA rounding EXACTLY: t_ctrl = fl( fl(t*(K-1)) * fl(1/(N-1)) )
    float tv = (m < M) ? t[m] : 0.0f;
    float tc = __fmul_rn(__fmul_rn(tv, km1), rcp);
    int i = min(max((int)floorf(tc), 0), K - 2);
    float u = tc - (float)i;

    // ---- cooperative fetch via cp.async.cg: 8 x 16B per lane,
    //      each group of 4 lanes covers one whole 128B record ----
    int r = lane & 7;
    int dq = lane >> 3;
    #pragma unroll
    for (int step = 0; step < 8; ++step) {
        int q = step * 4 + dq;
        int idx = __shfl_sync(0xffffffffu, i, q);
        const float4* src = &g_rec[(size_t)idx * 8 + r];
        uint32_t dst = (uint32_t)__cvta_generic_to_shared(
            &ws4[q * 8 + (r ^ (q & 7))]);          // XOR swizzle: conflict-free
        CP_ASYNC16(dst, src);
    }
    CP_ASYNC_COMMIT();
    CP_ASYNC_WAIT0();
    __syncwarp();

    // ---- read own record: 8 conflict-free LDS.128 ----
    int q7 = lane & 7;
    float4 P0 = ws4[lane * 8 + (0 ^ q7)];
    float4 P1 = ws4[lane * 8 + (1 ^ q7)];
    float4 P2 = ws4[lane * 8 + (2 ^ q7)];
    float4 P3 = ws4[lane * 8 + (3 ^ q7)];
    float4 P4 = ws4[lane * 8 + (4 ^ q7)];
    float4 P5 = ws4[lane * 8 + (5 ^ q7)];
    float4 P6 = ws4[lane * 8 + (6 ^ q7)];
    float4 P7 = ws4[lane * 8 + (7 ^ q7)];

    // ---- compute ----
    float u2 = u * u;
    float u3 = u2 * u;
    float h00 = 2.0f * u3 - 3.0f * u2 + 1.0f;
    float h10 = u3 - 2.0f * u2 + u;
    float h01 = -2.0f * u3 + 3.0f * u2;
    float h11 = u3 - u2;

    float Tx = h00 * P0.x + h10 * P0.w + h01 * P1.z + h11 * P2.y;
    float Ty = h00 * P0.y + h10 * P1.x + h01 * P1.w + h11 * P2.z;
    float Tz = h00 * P0.z + h10 * P1.y + h01 * P2.x + h11 * P2.w;

    float thm = P5.x, ism = P5.y, tha = P5.z, isa = P5.w;
    float w0m, w1m;
    if (ism != 0.0f) {
        w0m = __sinf((1.0f - u) * thm) * ism;
        w1m = __sinf(u * thm) * ism;
    } else {
        w0m = 1.0f - u;
        w1m = u;
    }
    float4 s_main = make_float4(w0m * P3.x + w1m * P4.x,
                                w0m * P3.y + w1m * P4.y,
                                w0m * P3.z + w1m * P4.z,
                                w0m * P3.w + w1m * P4.w);
    float w0a, w1a;
    if (isa != 0.0f) {
        w0a = __sinf((1.0f - u) * tha) * isa;
        w1a = __sinf(u * tha) * isa;
    } else {
        w0a = 1.0f - u;
        w1a = u;
    }
    float4 s_aux = make_float4(w0a * P6.x + w1a * P7.x,
                               w0a * P6.y + w1a * P7.y,
                               w0a * P6.z + w1a * P7.z,
                               w0a * P6.w + w1a * P7.w);

    // blend slerp: theta via fast poly acos (arg in [0,1] by construction)
    float vbl = 2.0f * u * (1.0f - u);
    float dotb = s_main.x*s_aux.x + s_main.y*s_aux.y + s_main.z*s_aux.z + s_main.w*s_aux.w;
    dotb = fminf(fmaxf(dotb, -1.0f), 1.0f);
    float sgnb = (dotb < 0.0f) ? -1.0f : 1.0f;
    float adb = fminf(fabsf(dotb), 1.0f);
    float thb = facos01(adb);
    float stb = __sinf(thb);
    float w0b, w1b;
    if (fabsf(stb) > 1e-6f) {
        float inv = __frcp_rn(stb);
        w0b = __sinf((1.0f - vbl) * thb) * inv;
        w1b = __sinf(vbl * thb) * inv;
    } else {
        w0b = 1.0f - vbl;
        w1b = vbl;
    }
    w1b *= sgnb;
    // raw (unnormalized) blended quat; normalization folded into R scale
    float w = w0b * s_main.x + w1b * s_aux.x;
    float x = w0b * s_main.y + w1b * s_aux.y;
    float y = w0b * s_main.z + w1b * s_aux.z;
    float z = w0b * s_main.w + w1b * s_aux.w;

    float n = w * w + x * x + y * y + z * z;
    float sS = 2.0f * __frcp_rn(n);        // R entries are quadratic in q: /n == normalize
    float xx = x * x, yy = y * y, zz = z * z;
    float xy = x * y, xz = x * z, yz = y * z;
    float wx = w * x, wy = w * y, wz = w * z;

    __syncwarp();   // all record reads done before staging overwrites them

    // ---- scatter outputs: R at q*9+c (9 coprime 32), T at 288+q*3+c ----
    if (m < M) {
        float* rr = wsf + lane * 9;
        rr[0] = 1.0f - sS * (yy + zz);
        rr[1] = sS * (xy - wz);
        rr[2] = sS * (xz + wy);
        rr[3] = sS * (xy + wz);
        rr[4] = 1.0f - sS * (xx + zz);
        rr[5] = sS * (yz - wx);
        rr[6] = sS * (xz - wy);
        rr[7] = sS * (yz + wx);
        rr[8] = 1.0f - sS * (xx + yy);
        float* tt = wsf + 288 + lane * 3;
        tt[0] = Tx; tt[1] = Ty; tt[2] = Tz;
    }
    __syncwarp();

    // ---- warp-local coalesced writeback (evict-first stores) ----
    int count = min(32, M - warpBase);
    if (count <= 0) return;

    if (count == 32) {
        float4* dstR = (float4*)(out + (size_t)warpBase * 9);   // warpBase%32==0 -> aligned
        const float4* srcR = (const float4*)wsf;
        #pragma unroll
        for (int n2 = lane; n2 < 72; n2 += 32)
            __stcs(dstR + n2, srcR[n2]);
        size_t tBase = (size_t)M * 9 + (size_t)warpBase * 3;
        if ((tBase & 3) == 0) {
            float4* dstT = (float4*)(out + tBase);
            const float4* srcT = (const float4*)(wsf + 288);
            if (lane < 24)
                __stcs(dstT + lane, srcT[lane]);
        } else {
            float* dstT = out + tBase;
            for (int e = lane; e < 96; e += 32)
                dstT[e] = wsf[288 + e];
        }
    } else {
        float* dstR = out + (size_t)warpBase * 9;
        for (int e = lane; e < count * 9; e += 32)
            dstR[e] = wsf[e];
        float* dstT = out + (size_t)M * 9 + (size_t)warpBase * 3;
        for (int e = lane; e < count * 3; e += 32)
            dstT[e] = wsf[288 + e];
    }
}

// ---------------------------------------------------------------------------
// Fallback for K-1 > CAPI: direct gather.
// ---------------------------------------------------------------------------
__global__ __launch_bounds__(256)
void camera_spline_kernel_direct(const float* __restrict__ t,
                                 const float* __restrict__ ctrl_trans,
                                 const float* __restrict__ ctrl_quats,
                                 const int* __restrict__ Nptr,
                                 float* __restrict__ out,
                                 int M, int K)
{
    int m = blockIdx.x * blockDim.x + threadIdx.x;
    if (m >= M) return;

    int N = __ldg(Nptr);
    float km1 = (float)(K - 1);
    float nm1 = (float)max(N - 1, 1);
    float rcp = __fdiv_rn(1.0f, nm1);
    float tc = __fmul_rn(__fmul_rn(t[m], km1), rcp);
    int i = min(max((int)floorf(tc), 0), K - 2);
    float u = tc - (float)i;
    int im1 = max(i - 1, 0);
    int ip2 = min(i + 2, K - 1);

    float3 p0 = make_float3(ctrl_trans[3*i+0], ctrl_trans[3*i+1], ctrl_trans[3*i+2]);
    float3 p1 = make_float3(ctrl_trans[3*(i+1)+0], ctrl_trans[3*(i+1)+1], ctrl_trans[3*(i+1)+2]);
    float3 pm = make_float3(ctrl_trans[3*im1+0], ctrl_trans[3*im1+1], ctrl_trans[3*im1+2]);
    float3 pp = make_float3(ctrl_trans[3*ip2+0], ctrl_trans[3*ip2+1], ctrl_trans[3*ip2+2]);

    float3 d01 = make_float3(p1.x - p0.x, p1.y - p0.y, p1.z - p0.z);
    float3 m0 = (i > 0) ? make_float3(0.5f*(p1.x-pm.x), 0.5f*(p1.y-pm.y), 0.5f*(p1.z-pm.z)) : d01;
    float3 m1 = (i + 1 < K - 1) ? make_float3(0.5f*(pp.x-p0.x), 0.5f*(pp.y-p0.y), 0.5f*(pp.z-p0.z)) : d01;

    float u2 = u * u, u3 = u2 * u;
    float h00 = 2.0f*u3 - 3.0f*u2 + 1.0f;
    float h10 = u3 - 2.0f*u2 + u;
    float h01 = -2.0f*u3 + 3.0f*u2;
    float h11 = u3 - u2;
    float Tx = h00*p0.x + h10*m0.x + h01*p1.x + h11*m1.x;
    float Ty = h00*p0.y + h10*m0.y + h01*p1.y + h11*m1.y;
    float Tz = h00*p0.z + h10*m0.z + h01*p1.z + h11*m1.z;

    const float4* quats = (const float4*)ctrl_quats;
    float4 q_i  = qnormalize(quats[i]);
    float4 q_i1 = qnormalize(quats[i + 1]);
    float4 q_m  = qnormalize(quats[im1]);
    float4 q_p  = qnormalize(quats[ip2]);
    float4 s_main = qslerp(q_i, q_i1, u);
    float4 s_aux  = qslerp(q_m, q_p, u);
    float4 q = qnormalize(qslerp(s_main, s_aux, 2.0f * u * (1.0f - u)));

    float w = q.x, x = q.y, y = q.z, z = q.w;
    float* R = out + (size_t)m * 9;
    R[0] = 1.0f - 2.0f * (y*y + z*z);
    R[1] = 2.0f * (x*y - w*z);
    R[2] = 2.0f * (x*z + w*y);
    R[3] = 2.0f * (x*y + w*z);
    R[4] = 1.0f - 2.0f * (x*x + z*z);
    R[5] = 2.0f * (y*z - w*x);
    R[6] = 2.0f * (x*z - w*y);
    R[7] = 2.0f * (y*z + w*x);
    R[8] = 1.0f - 2.0f * (x*x + y*y);
    float* Tout = out + (size_t)M * 9 + (size_t)m * 3;
    Tout[0] = Tx; Tout[1] = Ty; Tout[2] = Tz;
}

extern "C" void kernel_launch(void* const* d_in, const int* in_sizes, int n_in,
                              void* d_out, int out_size)
{
    const float* t          = (const float*)d_in[0];
    const float* ctrl_trans = (const float*)d_in[1];
    const float* ctrl_quats = (const float*)d_in[2];
    const int*   Nptr       = (const int*)d_in[3];

    int M = in_sizes[0];
    int K = in_sizes[1] / 3;

    float* out = (float*)d_out;

    if (K - 1 <= CAPI) {
        int nIv = K - 1;
        int pblocks = (nIv + TPB - 1) / TPB;
        precompute_intervals<<<pblocks, TPB>>>(ctrl_trans, ctrl_quats, Nptr, K);
        int blocks = (M + TPB - 1) / TPB;
        camera_spline_kernel<<<blocks, TPB>>>(t, out, M, K);
    } else {
        int blocks = (M + 255) / 256;
        camera_spline_kernel_direct<<<blocks, 256>>>(t, ctrl_trans, ctrl_quats, Nptr, out, M, K);
    }
}